// round 8
// baseline (speedup 1.0000x reference)
#include <cuda_runtime.h>

#define T_STEPS 512
#define BATCH   2048
#define IN_DIM  28
#define H_DIM   64
#define G_DIM   256      // 4*H
#define OUT_DIM 10
#define NB      16       // batch elements per CTA
#define NTHR    512
#define NCTA    (BATCH / NB)   // 128
#define XPAD    32       // xh row stride (floats)
#define GS      256      // Ws row stride (floats)

// Layer-0 hidden output scratch: [T][B][H] fp32
__device__ float g_h1[(long long)T_STEPS * BATCH * H_DIM];

static __device__ __forceinline__ float tanh_fast(float x) {
    float y;
    asm("tanh.approx.f32 %0, %1;" : "=f"(y) : "f"(x));
    return y;
}
static __device__ __forceinline__ float sig_fast(float x) {
    return fmaf(0.5f, tanh_fast(0.5f * x), 0.5f);
}
static __device__ __forceinline__ void ffma2(unsigned long long& d,
                                             unsigned long long a,
                                             unsigned long long b) {
    asm("fma.rn.f32x2 %0, %1, %2, %0;" : "+l"(d) : "l"(a), "l"(b));
}
static __device__ __forceinline__ void fadd2(unsigned long long& d,
                                             unsigned long long a) {
    asm("add.rn.f32x2 %0, %0, %1;" : "+l"(d) : "l"(a));
}
static __device__ __forceinline__ float2 u2f(unsigned long long v) {
    return *reinterpret_cast<float2*>(&v);
}

// Per-k-quarter bank skew (floats). Chosen so that within a warp the 8
// (kq, go) w-chunks land on {0,4,8,12,16,20,24,28} mod 32 -> conflict-free,
// and the 16 (kq, bq) x-chunks pack into the 2-wavefront minimum.
static __device__ __host__ __forceinline__ int skq(int q) {
    return (q & 1) * 4 + (q >> 1) * 16;   // 0, 4, 16, 20
}

// Thread map (tid 0..511), lane = tid & 31:
//   bq = lane & 3            batch quad -> b in [4bq, 4bq+4)
//   kq = (lane >> 2) & 3     k-quarter  -> shfl_xor(8) then shfl_xor(4)
//   go = tid >> 4            u-pair 0..31 (u = 2go, 2go+1); 2 go values/warp
// Weight columns permuted: g' = 8*go + e, e = [i u0, i u1, f u0, f u1,
//                                              g u0, g u1, o u0, o u1]
// After reduction, thread keeps batch column q == kq -> cell update for
// b = 4*bq + kq, units (2go, 2go+1); c lives in 2 registers.

template<int KD>
static __device__ __forceinline__ void gate_tile(
    const float* __restrict__ wr, const float* __restrict__ xp,
    const unsigned long long* bias_p, int kq, unsigned long long acc[4][4])
{
    constexpr int KH = KD / 4;

#pragma unroll
    for (int p = 0; p < 4; p++)
#pragma unroll
        for (int q = 0; q < 4; q++)
            acc[p][q] = (kq == 0) ? bias_p[p] : 0ull;

    ulonglong2 w0a = *reinterpret_cast<const ulonglong2*>(wr);
    ulonglong2 w0b = *reinterpret_cast<const ulonglong2*>(wr + 4);
    ulonglong2 x0a = *reinterpret_cast<const ulonglong2*>(xp);
    ulonglong2 x0b = *reinterpret_cast<const ulonglong2*>(xp + 4);

#pragma unroll 2
    for (int kk = 0; kk < KH; kk++) {
        ulonglong2 w1a, w1b, x1a, x1b;
        if (kk + 1 < KH) {
            const float* wn = wr + (kk + 1) * GS;
            const float* xn = xp + (kk + 1) * XPAD;
            w1a = *reinterpret_cast<const ulonglong2*>(wn);
            w1b = *reinterpret_cast<const ulonglong2*>(wn + 4);
            x1a = *reinterpret_cast<const ulonglong2*>(xn);
            x1b = *reinterpret_cast<const ulonglong2*>(xn + 4);
        }
        unsigned long long wp[4] = {w0a.x, w0a.y, w0b.x, w0b.y};
        unsigned long long xd[4] = {x0a.x, x0a.y, x0b.x, x0b.y};
#pragma unroll
        for (int p = 0; p < 4; p++)
#pragma unroll
            for (int q = 0; q < 4; q++)
                ffma2(acc[p][q], wp[p], xd[q]);
        w0a = w1a; w0b = w1b; x0a = x1a; x0b = x1b;
    }
}

// keep/send two-stage reduction over kq; fin[p] is final for q == kq
static __device__ __forceinline__ void kq_reduce(
    unsigned long long acc[4][4], int kq, unsigned long long fin[4])
{
    const int bit1 = (kq >> 1) & 1;
    const int bit0 = kq & 1;

    unsigned long long keep[4][2];
#pragma unroll
    for (int p = 0; p < 4; p++)
#pragma unroll
        for (int qq = 0; qq < 2; qq++) {
            int q_keep = 2 * bit1 + qq;
            int q_send = 2 * (1 - bit1) + qq;
            unsigned long long r = __shfl_xor_sync(0xFFFFFFFFu, acc[p][q_send], 8);
            keep[p][qq] = acc[p][q_keep];
            fadd2(keep[p][qq], r);
        }
#pragma unroll
    for (int p = 0; p < 4; p++) {
        unsigned long long r = __shfl_xor_sync(0xFFFFFFFFu, keep[p][1 - bit0], 4);
        fin[p] = keep[p][bit0];
        fadd2(fin[p], r);
    }
}

// permuted column -> original gate row
static __device__ __forceinline__ int gperm(int gp) {
    int e = gp & 7, j = gp >> 3;
    return (e >> 1) * H_DIM + 2 * j + (e & 1);
}

// skewed row base for Ws / xh (row = global k index)
template<int KD>
static __device__ __forceinline__ int wrow(int row) {
    constexpr int KH = KD / 4;
    int q = row / KH;
    return q * KH * GS + skq(q) + (row - q * KH) * GS;
}
template<int KD>
static __device__ __forceinline__ int xrow(int row) {
    constexpr int KH = KD / 4;
    int q = row / KH;
    return q * KH * XPAD + skq(q) + (row - q * KH) * XPAD;
}

// ---------------------------------------------------------------------------
// Layer 0: x[2048,512,28] -> h1 scratch   (KD=92, KH=23)
// ---------------------------------------------------------------------------
__global__ void __launch_bounds__(NTHR, 1)
lstm_l0(const float* __restrict__ x,
        const float* __restrict__ Wih, const float* __restrict__ Whh,
        const float* __restrict__ bih, const float* __restrict__ bhh)
{
    constexpr int KD = IN_DIM + H_DIM;  // 92
    constexpr int KH = KD / 4;          // 23
    extern __shared__ float sm[];
    float* Ws   = sm;                        // KD*GS + 20 (skewed quarters)
    float* bias = Ws + KD * GS + 32;         // [256] permuted
    float* xh   = bias + G_DIM;              // KD*XPAD + 20 (skewed quarters)

    const int tid = threadIdx.x;
    const int b0  = blockIdx.x * NB;

    for (int i = tid; i < IN_DIM * G_DIM; i += NTHR) {
        int k = i >> 8, gp = i & 255;
        Ws[wrow<KD>(k) + gp] = Wih[gperm(gp) * IN_DIM + k];
    }
    for (int i = tid; i < H_DIM * G_DIM; i += NTHR) {
        int k = i >> 8, gp = i & 255;
        Ws[wrow<KD>(IN_DIM + k) + gp] = Whh[gperm(gp) * H_DIM + k];
    }
    for (int gp = tid; gp < G_DIM; gp += NTHR) {
        int g = gperm(gp);
        bias[gp] = bih[g] + bhh[g];
    }
    for (int i = tid; i < KD * XPAD + 32; i += NTHR) xh[i] = 0.0f;
    __syncthreads();

    const int lane = tid & 31;
    const int bq = lane & 3;
    const int kq = (lane >> 2) & 3;
    const int go = tid >> 4;
    const int u0 = 2 * go;
    const int bc = 4 * bq + kq;

    // hoisted operand bases for this thread
    const float* wr = Ws + kq * KH * GS   + skq(kq) + go * 8;
    const float* xp = xh + kq * KH * XPAD + skq(kq) + bq * 8;
    // hoisted h-row addresses (rows may straddle quarters -> per-row calc)
    const int ha0 = xrow<KD>(IN_DIM + u0)     + 2 * bc;
    const int ha1 = xrow<KD>(IN_DIM + u0 + 1) + 2 * bc;

    unsigned long long bias_p[4];
#pragma unroll
    for (int p = 0; p < 4; p++)
        bias_p[p] = *reinterpret_cast<const unsigned long long*>(bias + go * 8 + 2 * p);

    float c0 = 0.0f, c1 = 0.0f;

    // prefetch x_0 (448 items over 512 threads)
    float xr = 0.0f;
    int xbl = 0, xk = 0, xaddr = 0;
    const bool xact = (tid < NB * IN_DIM);
    if (xact) {
        xbl = tid / IN_DIM; xk = tid % IN_DIM;
        xaddr = xrow<KD>(xk) + 2 * xbl;
        xr = x[((long long)(b0 + xbl) * T_STEPS) * IN_DIM + xk];
    }

    for (int t = 0; t < T_STEPS; t++) {
        if (xact)
            *reinterpret_cast<float2*>(xh + xaddr) = make_float2(xr, xr);
        __syncthreads();   // bar1: x_t + h_{t-1} visible

        if (xact && t + 1 < T_STEPS)
            xr = x[((long long)(b0 + xbl) * T_STEPS + (t + 1)) * IN_DIM + xk];

        unsigned long long acc[4][4];
        gate_tile<KD>(wr, xp, bias_p, kq, acc);

        unsigned long long fin[4];
        kq_reduce(acc, kq, fin);

        float2 iv = u2f(fin[0]), fv = u2f(fin[1]);
        float2 gv = u2f(fin[2]), ov = u2f(fin[3]);
        float h0, h1;
        {
            float i_ = sig_fast(iv.x), f_ = sig_fast(fv.x);
            float g_ = tanh_fast(gv.x), o_ = sig_fast(ov.x);
            c0 = fmaf(f_, c0, i_ * g_);
            h0 = o_ * tanh_fast(c0);
        }
        {
            float i_ = sig_fast(iv.y), f_ = sig_fast(fv.y);
            float g_ = tanh_fast(gv.y), o_ = sig_fast(ov.y);
            c1 = fmaf(f_, c1, i_ * g_);
            h1 = o_ * tanh_fast(c1);
        }
        __syncthreads();   // bar2: all xh reads of step t done before h writes

        *reinterpret_cast<float2*>(xh + ha0) = make_float2(h0, h0);
        *reinterpret_cast<float2*>(xh + ha1) = make_float2(h1, h1);
        *reinterpret_cast<float2*>(
            g_h1 + ((long long)t * BATCH + b0 + bc) * H_DIM + u0) =
            make_float2(h0, h1);
        // bar1 of next iteration orders these stores before next gemm reads
    }
}

// ---------------------------------------------------------------------------
// Layer 1: h1 -> h2; writes out[2048,10] and r_last[2048,64]  (KD=128, KH=32)
// ---------------------------------------------------------------------------
__global__ void __launch_bounds__(NTHR, 1)
lstm_l1(const float* __restrict__ Wih, const float* __restrict__ Whh,
        const float* __restrict__ bih, const float* __restrict__ bhh,
        const float* __restrict__ Wout, const float* __restrict__ bout,
        float* __restrict__ dout)
{
    constexpr int KD = H_DIM + H_DIM;   // 128
    constexpr int KH = KD / 4;          // 32
    extern __shared__ float sm[];
    float* Ws   = sm;                        // KD*GS + 20 (skewed quarters)
    float* bias = Ws + KD * GS + 32;
    float* xh   = bias + G_DIM;              // rows 0..63 h1, 64..127 h2

    const int tid = threadIdx.x;
    const int b0  = blockIdx.x * NB;

    for (int i = tid; i < H_DIM * G_DIM; i += NTHR) {
        int k = i >> 8, gp = i & 255;
        Ws[wrow<KD>(k) + gp] = Wih[gperm(gp) * H_DIM + k];
    }
    for (int i = tid; i < H_DIM * G_DIM; i += NTHR) {
        int k = i >> 8, gp = i & 255;
        Ws[wrow<KD>(H_DIM + k) + gp] = Whh[gperm(gp) * H_DIM + k];
    }
    for (int gp = tid; gp < G_DIM; gp += NTHR) {
        int g = gperm(gp);
        bias[gp] = bih[g] + bhh[g];
    }
    for (int i = tid; i < KD * XPAD + 32; i += NTHR) xh[i] = 0.0f;
    __syncthreads();

    const int lane = tid & 31;
    const int bq = lane & 3;
    const int kq = (lane >> 2) & 3;
    const int go = tid >> 4;
    const int u0 = 2 * go;
    const int bc = 4 * bq + kq;

    const float* wr = Ws + kq * KH * GS   + skq(kq) + go * 8;
    const float* xp = xh + kq * KH * XPAD + skq(kq) + bq * 8;
    const int ha0 = xrow<KD>(H_DIM + u0)     + 2 * bc;
    const int ha1 = xrow<KD>(H_DIM + u0 + 1) + 2 * bc;

    unsigned long long bias_p[4];
#pragma unroll
    for (int p = 0; p < 4; p++)
        bias_p[p] = *reinterpret_cast<const unsigned long long*>(bias + go * 8 + 2 * p);

    float c0 = 0.0f, c1 = 0.0f;

    // prefetch h1_0 (1024 items, 2 per thread, coalesced)
    float hr[2];
    int   haddr[2];
#pragma unroll
    for (int j = 0; j < 2; j++) {
        int idx = tid + j * NTHR;
        int bl = idx >> 6, u = idx & 63;
        haddr[j] = xrow<KD>(u) + 2 * bl;
        hr[j] = g_h1[(long long)(b0 + bl) * H_DIM + u];
    }

    for (int t = 0; t < T_STEPS; t++) {
#pragma unroll
        for (int j = 0; j < 2; j++)
            *reinterpret_cast<float2*>(xh + haddr[j]) = make_float2(hr[j], hr[j]);
        __syncthreads();   // bar1

        if (t + 1 < T_STEPS) {
#pragma unroll
            for (int j = 0; j < 2; j++) {
                int idx = tid + j * NTHR;
                int bl = idx >> 6, u = idx & 63;
                hr[j] = g_h1[((long long)(t + 1) * BATCH + b0 + bl) * H_DIM + u];
            }
        }

        unsigned long long acc[4][4];
        gate_tile<KD>(wr, xp, bias_p, kq, acc);

        unsigned long long fin[4];
        kq_reduce(acc, kq, fin);

        float2 iv = u2f(fin[0]), fv = u2f(fin[1]);
        float2 gv = u2f(fin[2]), ov = u2f(fin[3]);
        float h0, h1;
        {
            float i_ = sig_fast(iv.x), f_ = sig_fast(fv.x);
            float g_ = tanh_fast(gv.x), o_ = sig_fast(ov.x);
            c0 = fmaf(f_, c0, i_ * g_);
            h0 = o_ * tanh_fast(c0);
        }
        {
            float i_ = sig_fast(iv.y), f_ = sig_fast(fv.y);
            float g_ = tanh_fast(gv.y), o_ = sig_fast(ov.y);
            c1 = fmaf(f_, c1, i_ * g_);
            h1 = o_ * tanh_fast(c1);
        }
        __syncthreads();   // bar2

        *reinterpret_cast<float2*>(xh + ha0) = make_float2(h0, h0);
        *reinterpret_cast<float2*>(xh + ha1) = make_float2(h1, h1);
    }
    __syncthreads();   // final h2 visible

    // r_last (1024 items, 2 per thread)
#pragma unroll
    for (int j = 0; j < 2; j++) {
        int idx = tid + j * NTHR;
        int bl = idx >> 6, u = idx & 63;
        dout[(long long)BATCH * OUT_DIM + (long long)(b0 + bl) * H_DIM + u] =
            xh[xrow<KD>(H_DIM + u) + 2 * bl];
    }
    // out = h2 @ Wout^T + bout (160 items over 512 threads)
    for (int i = tid; i < NB * OUT_DIM; i += NTHR) {
        int bl = i / OUT_DIM, o = i % OUT_DIM;
        float s = bout[o];
#pragma unroll
        for (int u = 0; u < H_DIM; u++)
            s = fmaf(xh[xrow<KD>(H_DIM + u) + 2 * bl], Wout[o * H_DIM + u], s);
        dout[(long long)(b0 + bl) * OUT_DIM + o] = s;
    }
}

// ---------------------------------------------------------------------------
extern "C" void kernel_launch(void* const* d_in, const int* in_sizes, int n_in,
                              void* d_out, int out_size)
{
    const float* x    = (const float*)d_in[0];
    const float* Wih0 = (const float*)d_in[1];
    const float* Whh0 = (const float*)d_in[2];
    const float* bih0 = (const float*)d_in[3];
    const float* bhh0 = (const float*)d_in[4];
    const float* Wih1 = (const float*)d_in[5];
    const float* Whh1 = (const float*)d_in[6];
    const float* bih1 = (const float*)d_in[7];
    const float* bhh1 = (const float*)d_in[8];
    const float* Wout = (const float*)d_in[9];
    const float* bout = (const float*)d_in[10];
    float* out = (float*)d_out;

    const int KD0 = IN_DIM + H_DIM, KD1 = 2 * H_DIM;
    const int smA = (KD0 * GS + 32 + G_DIM + KD0 * XPAD + 32) * 4;
    const int smB = (KD1 * GS + 32 + G_DIM + KD1 * XPAD + 32) * 4;

    cudaFuncSetAttribute(lstm_l0, cudaFuncAttributeMaxDynamicSharedMemorySize, smA);
    cudaFuncSetAttribute(lstm_l1, cudaFuncAttributeMaxDynamicSharedMemorySize, smB);

    lstm_l0<<<NCTA, NTHR, smA>>>(x, Wih0, Whh0, bih0, bhh0);
    lstm_l1<<<NCTA, NTHR, smB>>>(Wih1, Whh1, bih1, bhh1, Wout, bout, out);
}

// round 9
// speedup vs baseline: 1.3771x; 1.3771x over previous
#include <cuda_runtime.h>

#define T_STEPS 512
#define BATCH   2048
#define IN_DIM  28
#define H_DIM   64
#define G_DIM   256      // 4*H
#define OUT_DIM 10
#define NB      16       // batch elements per CTA
#define NTHR    256
#define NCTA    (BATCH / NB)   // 128
#define XPAD    32       // xh row stride (floats)
#define SKEW    4        // +16B for rows in the second k-half (bank separation)

// Layer-0 hidden output scratch: [T][B][H] fp32
__device__ float g_h1[(long long)T_STEPS * BATCH * H_DIM];

typedef unsigned long long ull;

static __device__ __forceinline__ float tanh_fast(float x) {
    float y;
    asm("tanh.approx.f32 %0, %1;" : "=f"(y) : "f"(x));
    return y;
}
static __device__ __forceinline__ float sig_fast(float x) {
    return fmaf(0.5f, tanh_fast(0.5f * x), 0.5f);
}
static __device__ __forceinline__ void ffma2(ull& d, ull a, ull b) {
    asm("fma.rn.f32x2 %0, %1, %2, %0;" : "+l"(d) : "l"(a), "l"(b));
}
static __device__ __forceinline__ void fadd2(ull& d, ull a) {
    asm("add.rn.f32x2 %0, %0, %1;" : "+l"(d) : "l"(a));
}
static __device__ __forceinline__ float2 u2f(ull v) {
    return *reinterpret_cast<float2*>(&v);
}
static __device__ __forceinline__ ull pack2(float a, float b) {
    float2 f = make_float2(a, b);
    return *reinterpret_cast<ull*>(&f);
}

// Thread map (tid 0..255), lane = tid & 31:
//   p     = lane & 3          gate type (0:i 1:f 2:g 3:o)
//   kh    = (lane >> 2) & 1   k-half
//   upl   = (lane >> 3) & 3   u-pair low bits
//   upair = (tid >> 5)*4+upl  u-pair 0..31 (units u0=2*upair, u0+1)
// Thread holds weights W[g0..g0+1][k-half] in regs, g0 = p*64 + 2*upair.
// acc[j] (j=0..15) = {gate-p(u0), gate-p(u1)} partial for batch j.
// Reduction: shfl_xor(4) over kh, then 2-stage p-transpose (xor 1, xor 2)
// leaving each thread i,f,g,o for 2 batches x 2 units. c stays in 4 regs.

// ---------------------------------------------------------------------------
// Layer 0: x[2048,512,28] -> h1 scratch   (K=92, KH=46)
// ---------------------------------------------------------------------------
__global__ void __launch_bounds__(NTHR, 1)
lstm_l0(const float* __restrict__ x,
        const float* __restrict__ Wih, const float* __restrict__ Whh,
        const float* __restrict__ bih, const float* __restrict__ bhh)
{
    constexpr int KD = IN_DIM + H_DIM;  // 92
    constexpr int KH = KD / 2;          // 46
    extern __shared__ float sm[];
    float* xh = sm;                     // rows: 0..27 x, 28..91 h; skew for row>=46

    const int tid = threadIdx.x;
    const int b0  = blockIdx.x * NB;

    for (int i = tid; i < KD * XPAD + SKEW; i += NTHR) xh[i] = 0.0f;

    const int lane  = tid & 31;
    const int p     = lane & 3;
    const int kh    = (lane >> 2) & 1;
    const int upl   = (lane >> 3) & 3;
    const int upair = (tid >> 5) * 4 + upl;
    const int u0    = 2 * upair;
    const int g0    = p * H_DIM + u0;
    const int pb0   = p & 1;
    const int pb1   = (p >> 1) & 1;
    const int B0    = kh * 8 + pb0 * 4 + pb1 * 2;  // first of 2 owned batches

    // weights into registers: w[kk] = {W[g0][k], W[g0+1][k]}, k = kh*KH + kk
    ull w[KH];
#pragma unroll
    for (int kk = 0; kk < KH; kk++) {
        int k = kh * KH + kk;
        float a, b;
        if (k < IN_DIM) {
            a = Wih[g0 * IN_DIM + k];
            b = Wih[(g0 + 1) * IN_DIM + k];
        } else {
            a = Whh[g0 * H_DIM + (k - IN_DIM)];
            b = Whh[(g0 + 1) * H_DIM + (k - IN_DIM)];
        }
        w[kk] = pack2(a, b);
    }
    const ull biasu = pack2(bih[g0] + bhh[g0], bih[g0 + 1] + bhh[g0 + 1]);

    float c0 = 0.f, c1 = 0.f, c2 = 0.f, c3 = 0.f;   // cells: (B0,u0)(B0,u1)(B0+1,u0)(B0+1,u1)

    // h-store rows (skew applies when row >= KH; u0 pair never straddles)
    const int hrow = IN_DIM + u0;
    const int hsk  = (hrow >= KH) ? SKEW : 0;
    float* hst0 = xh + hrow * XPAD + hsk + 2 * B0;
    float* hst1 = xh + (hrow + 1) * XPAD + hsk + 2 * B0;

    // x operand base for this thread's k-half (x rows < 46: skew only kh=1 h rows)
    const float* xbase = xh + kh * (KH * XPAD + SKEW);

    // prefetch x_0 (448 items over 256 threads)
    float xr[2];
    int   xaddr[2];
    bool  xact[2];
#pragma unroll
    for (int j = 0; j < 2; j++) {
        int idx = tid + j * NTHR;
        xact[j] = idx < NB * IN_DIM;
        if (xact[j]) {
            int bl = idx / IN_DIM, k = idx % IN_DIM;
            xaddr[j] = k * XPAD + 2 * bl;        // k < 28 < KH: no skew
            xr[j] = x[((long long)(b0 + bl) * T_STEPS) * IN_DIM + k];
        } else { xaddr[j] = 0; xr[j] = 0.f; }
    }

    for (int t = 0; t < T_STEPS; t++) {
#pragma unroll
        for (int j = 0; j < 2; j++)
            if (xact[j])
                *reinterpret_cast<float2*>(xh + xaddr[j]) = make_float2(xr[j], xr[j]);
        __syncthreads();   // bar1: x_t + h_{t-1} visible

        if (t + 1 < T_STEPS) {
#pragma unroll
            for (int j = 0; j < 2; j++)
                if (xact[j]) {
                    int idx = tid + j * NTHR;
                    int bl = idx / IN_DIM, k = idx % IN_DIM;
                    xr[j] = x[((long long)(b0 + bl) * T_STEPS + (t + 1)) * IN_DIM + k];
                }
        }

        // gate GEMM: weights from regs, x broadcast from smem
        ull acc[16];
#pragma unroll
        for (int j = 0; j < 16; j++) acc[j] = (kh == 0) ? biasu : 0ull;

#pragma unroll
        for (int kk = 0; kk < KH; kk++) {
            const float* xp = xbase + kk * XPAD;
            ull xd[16];
#pragma unroll
            for (int c = 0; c < 8; c++) {
                ulonglong2 v = *reinterpret_cast<const ulonglong2*>(xp + 4 * c);
                xd[2 * c] = v.x; xd[2 * c + 1] = v.y;
            }
#pragma unroll
            for (int j = 0; j < 16; j++) ffma2(acc[j], w[kk], xd[j]);
        }

        // kh reduce (xor 4): keep own 8 batches
        ull a1[8];
#pragma unroll
        for (int j = 0; j < 8; j++) {
            ull mine = kh ? acc[8 + j] : acc[j];
            ull send = kh ? acc[j] : acc[8 + j];
            ull r = __shfl_xor_sync(0xFFFFFFFFu, send, 4);
            fadd2(mine, r);
            a1[j] = mine;
        }
        // p-transpose stage 1 (xor 1): canonical [even-type tE, odd-type tO] x4 batches
        ull tE[4], tO[4];
#pragma unroll
        for (int i = 0; i < 4; i++) {
            ull mine = pb0 ? a1[4 + i] : a1[i];
            ull send = pb0 ? a1[i] : a1[4 + i];
            ull r = __shfl_xor_sync(0xFFFFFFFFu, send, 1);
            tE[i] = pb0 ? r : mine;
            tO[i] = pb0 ? mine : r;
        }
        // stage 2 (xor 2): canonical [i,f,g,o] x2 batches
        ull gi[2], gf[2], gg[2], go_[2];
#pragma unroll
        for (int i = 0; i < 2; i++) {
            ull mE = pb1 ? tE[2 + i] : tE[i];
            ull sE = pb1 ? tE[i] : tE[2 + i];
            ull mO = pb1 ? tO[2 + i] : tO[i];
            ull sO = pb1 ? tO[i] : tO[2 + i];
            ull rE = __shfl_xor_sync(0xFFFFFFFFu, sE, 2);
            ull rO = __shfl_xor_sync(0xFFFFFFFFu, sO, 2);
            gi[i]  = pb1 ? rE : mE;
            gf[i]  = pb1 ? rO : mO;
            gg[i]  = pb1 ? mE : rE;
            go_[i] = pb1 ? mO : rO;
        }

        // cell updates: batches B0, B0+1 x units u0, u0+1
        float h[4];
        {
            float2 iv = u2f(gi[0]), fv = u2f(gf[0]), gv = u2f(gg[0]), ov = u2f(go_[0]);
            c0 = fmaf(sig_fast(fv.x), c0, sig_fast(iv.x) * tanh_fast(gv.x));
            h[0] = sig_fast(ov.x) * tanh_fast(c0);
            c1 = fmaf(sig_fast(fv.y), c1, sig_fast(iv.y) * tanh_fast(gv.y));
            h[1] = sig_fast(ov.y) * tanh_fast(c1);
        }
        {
            float2 iv = u2f(gi[1]), fv = u2f(gf[1]), gv = u2f(gg[1]), ov = u2f(go_[1]);
            c2 = fmaf(sig_fast(fv.x), c2, sig_fast(iv.x) * tanh_fast(gv.x));
            h[2] = sig_fast(ov.x) * tanh_fast(c2);
            c3 = fmaf(sig_fast(fv.y), c3, sig_fast(iv.y) * tanh_fast(gv.y));
            h[3] = sig_fast(ov.y) * tanh_fast(c3);
        }
        __syncthreads();   // bar2: xh reads of step t complete before h writes

        *reinterpret_cast<float4*>(hst0) = make_float4(h[0], h[0], h[2], h[2]);
        *reinterpret_cast<float4*>(hst1) = make_float4(h[1], h[1], h[3], h[3]);
        float* gh = g_h1 + ((long long)t * BATCH + b0 + B0) * H_DIM + u0;
        *reinterpret_cast<float2*>(gh)          = make_float2(h[0], h[1]);
        *reinterpret_cast<float2*>(gh + H_DIM)  = make_float2(h[2], h[3]);
        // bar1 of next iteration orders these stores before next gemm reads
    }
}

// ---------------------------------------------------------------------------
// Layer 1: h1 -> h2; writes out[2048,10] and r_last[2048,64]  (K=128, KH=64)
// ---------------------------------------------------------------------------
__global__ void __launch_bounds__(NTHR, 1)
lstm_l1(const float* __restrict__ Wih, const float* __restrict__ Whh,
        const float* __restrict__ bih, const float* __restrict__ bhh,
        const float* __restrict__ Wout, const float* __restrict__ bout,
        float* __restrict__ dout)
{
    constexpr int KD = 2 * H_DIM;   // 128
    constexpr int KH = KD / 2;      // 64
    extern __shared__ float sm[];
    float* xh = sm;                 // rows 0..63 h1, 64..127 h2 (+SKEW)

    const int tid = threadIdx.x;
    const int b0  = blockIdx.x * NB;

    for (int i = tid; i < KD * XPAD + SKEW; i += NTHR) xh[i] = 0.0f;

    const int lane  = tid & 31;
    const int p     = lane & 3;
    const int kh    = (lane >> 2) & 1;
    const int upl   = (lane >> 3) & 3;
    const int upair = (tid >> 5) * 4 + upl;
    const int u0    = 2 * upair;
    const int g0    = p * H_DIM + u0;
    const int pb0   = p & 1;
    const int pb1   = (p >> 1) & 1;
    const int B0    = kh * 8 + pb0 * 4 + pb1 * 2;

    // kh=0 -> Wih1 rows (h1), kh=1 -> Whh1 rows (h2)
    const float* Wsel = kh ? Whh : Wih;
    ull w[KH];
#pragma unroll
    for (int kk = 0; kk < KH; kk++)
        w[kk] = pack2(Wsel[g0 * H_DIM + kk], Wsel[(g0 + 1) * H_DIM + kk]);
    const ull biasu = pack2(bih[g0] + bhh[g0], bih[g0 + 1] + bhh[g0 + 1]);

    float c0 = 0.f, c1 = 0.f, c2 = 0.f, c3 = 0.f;

    // h2 rows (64..127) all carry the skew
    float* hst0 = xh + (H_DIM + u0) * XPAD + SKEW + 2 * B0;
    float* hst1 = xh + (H_DIM + u0 + 1) * XPAD + SKEW + 2 * B0;
    const float* xbase = xh + kh * (KH * XPAD + SKEW);

    // prefetch h1_0 (1024 items, 4 per thread, coalesced)
    float hr[4];
    int   haddr[4];
#pragma unroll
    for (int j = 0; j < 4; j++) {
        int idx = tid + j * NTHR;
        int bl = idx >> 6, u = idx & 63;
        haddr[j] = u * XPAD + 2 * bl;          // u < 64: no skew
        hr[j] = g_h1[(long long)(b0 + bl) * H_DIM + u];
    }

    for (int t = 0; t < T_STEPS; t++) {
#pragma unroll
        for (int j = 0; j < 4; j++)
            *reinterpret_cast<float2*>(xh + haddr[j]) = make_float2(hr[j], hr[j]);
        __syncthreads();   // bar1

        if (t + 1 < T_STEPS) {
#pragma unroll
            for (int j = 0; j < 4; j++) {
                int idx = tid + j * NTHR;
                int bl = idx >> 6, u = idx & 63;
                hr[j] = g_h1[((long long)(t + 1) * BATCH + b0 + bl) * H_DIM + u];
            }
        }

        ull acc[16];
#pragma unroll
        for (int j = 0; j < 16; j++) acc[j] = (kh == 0) ? biasu : 0ull;

#pragma unroll
        for (int kk = 0; kk < KH; kk++) {
            const float* xp = xbase + kk * XPAD;
            ull xd[16];
#pragma unroll
            for (int c = 0; c < 8; c++) {
                ulonglong2 v = *reinterpret_cast<const ulonglong2*>(xp + 4 * c);
                xd[2 * c] = v.x; xd[2 * c + 1] = v.y;
            }
#pragma unroll
            for (int j = 0; j < 16; j++) ffma2(acc[j], w[kk], xd[j]);
        }

        ull a1[8];
#pragma unroll
        for (int j = 0; j < 8; j++) {
            ull mine = kh ? acc[8 + j] : acc[j];
            ull send = kh ? acc[j] : acc[8 + j];
            ull r = __shfl_xor_sync(0xFFFFFFFFu, send, 4);
            fadd2(mine, r);
            a1[j] = mine;
        }
        ull tE[4], tO[4];
#pragma unroll
        for (int i = 0; i < 4; i++) {
            ull mine = pb0 ? a1[4 + i] : a1[i];
            ull send = pb0 ? a1[i] : a1[4 + i];
            ull r = __shfl_xor_sync(0xFFFFFFFFu, send, 1);
            tE[i] = pb0 ? r : mine;
            tO[i] = pb0 ? mine : r;
        }
        ull gi[2], gf[2], gg[2], go_[2];
#pragma unroll
        for (int i = 0; i < 2; i++) {
            ull mE = pb1 ? tE[2 + i] : tE[i];
            ull sE = pb1 ? tE[i] : tE[2 + i];
            ull mO = pb1 ? tO[2 + i] : tO[i];
            ull sO = pb1 ? tO[i] : tO[2 + i];
            ull rE = __shfl_xor_sync(0xFFFFFFFFu, sE, 2);
            ull rO = __shfl_xor_sync(0xFFFFFFFFu, sO, 2);
            gi[i]  = pb1 ? rE : mE;
            gf[i]  = pb1 ? rO : mO;
            gg[i]  = pb1 ? mE : rE;
            go_[i] = pb1 ? mO : rO;
        }

        float h[4];
        {
            float2 iv = u2f(gi[0]), fv = u2f(gf[0]), gv = u2f(gg[0]), ov = u2f(go_[0]);
            c0 = fmaf(sig_fast(fv.x), c0, sig_fast(iv.x) * tanh_fast(gv.x));
            h[0] = sig_fast(ov.x) * tanh_fast(c0);
            c1 = fmaf(sig_fast(fv.y), c1, sig_fast(iv.y) * tanh_fast(gv.y));
            h[1] = sig_fast(ov.y) * tanh_fast(c1);
        }
        {
            float2 iv = u2f(gi[1]), fv = u2f(gf[1]), gv = u2f(gg[1]), ov = u2f(go_[1]);
            c2 = fmaf(sig_fast(fv.x), c2, sig_fast(iv.x) * tanh_fast(gv.x));
            h[2] = sig_fast(ov.x) * tanh_fast(c2);
            c3 = fmaf(sig_fast(fv.y), c3, sig_fast(iv.y) * tanh_fast(gv.y));
            h[3] = sig_fast(ov.y) * tanh_fast(c3);
        }
        __syncthreads();   // bar2

        *reinterpret_cast<float4*>(hst0) = make_float4(h[0], h[0], h[2], h[2]);
        *reinterpret_cast<float4*>(hst1) = make_float4(h[1], h[1], h[3], h[3]);
    }
    __syncthreads();   // final h2 visible

    // r_last (1024 items, 4 per thread); h2 rows carry SKEW
#pragma unroll
    for (int j = 0; j < 4; j++) {
        int idx = tid + j * NTHR;
        int bl = idx >> 6, u = idx & 63;
        dout[(long long)BATCH * OUT_DIM + (long long)(b0 + bl) * H_DIM + u] =
            xh[(H_DIM + u) * XPAD + SKEW + 2 * bl];
    }
    // out = h2 @ Wout^T + bout (160 items over 256 threads)
    for (int i = tid; i < NB * OUT_DIM; i += NTHR) {
        int bl = i / OUT_DIM, o = i % OUT_DIM;
        float s = bout[o];
#pragma unroll
        for (int u = 0; u < H_DIM; u++)
            s = fmaf(xh[(H_DIM + u) * XPAD + SKEW + 2 * bl], Wout[o * H_DIM + u], s);
        dout[(long long)(b0 + bl) * OUT_DIM + o] = s;
    }
}

// ---------------------------------------------------------------------------
extern "C" void kernel_launch(void* const* d_in, const int* in_sizes, int n_in,
                              void* d_out, int out_size)
{
    const float* x    = (const float*)d_in[0];
    const float* Wih0 = (const float*)d_in[1];
    const float* Whh0 = (const float*)d_in[2];
    const float* bih0 = (const float*)d_in[3];
    const float* bhh0 = (const float*)d_in[4];
    const float* Wih1 = (const float*)d_in[5];
    const float* Whh1 = (const float*)d_in[6];
    const float* bih1 = (const float*)d_in[7];
    const float* bhh1 = (const float*)d_in[8];
    const float* Wout = (const float*)d_in[9];
    const float* bout = (const float*)d_in[10];
    float* out = (float*)d_out;

    const int KD0 = IN_DIM + H_DIM, KD1 = 2 * H_DIM;
    const int smA = (KD0 * XPAD + SKEW) * 4;
    const int smB = (KD1 * XPAD + SKEW) * 4;

    cudaFuncSetAttribute(lstm_l0, cudaFuncAttributeMaxDynamicSharedMemorySize, smA);
    cudaFuncSetAttribute(lstm_l1, cudaFuncAttributeMaxDynamicSharedMemorySize, smB);

    lstm_l0<<<NCTA, NTHR, smA>>>(x, Wih0, Whh0, bih0, bhh0);
    lstm_l1<<<NCTA, NTHR, smB>>>(Wih1, Whh1, bih1, bhh1, Wout, bout, out);
}

// round 11
// speedup vs baseline: 5.6446x; 4.0988x over previous
#include <cuda_runtime.h>
#include <cuda_bf16.h>

typedef unsigned int u32;

#define T_STEPS 512
#define BATCH   2048
#define IN_DIM  28
#define H_DIM   64
#define OUT_DIM 10
#define NB      16
#define NTHR    256
#define NCTA    (BATCH / NB)   // 128
#define XS      136            // X row stride in bf16 elems (conflict-free)

// Layer-0 hidden output scratch: [T][B][H] fp32
__device__ float g_h1[(long long)T_STEPS * BATCH * H_DIM];

static __device__ __forceinline__ float tanh_fast(float x) {
    float y; asm("tanh.approx.f32 %0, %1;" : "=f"(y) : "f"(x)); return y;
}
static __device__ __forceinline__ float sig_fast(float x) {
    return fmaf(0.5f, tanh_fast(0.5f * x), 0.5f);
}
static __device__ __forceinline__ u32 pk(__nv_bfloat16 a, __nv_bfloat16 b) {
    __nv_bfloat162 t; t.x = a; t.y = b;
    return *reinterpret_cast<u32*>(&t);
}
static __device__ __forceinline__ u32 pkf(float a, float b) {
    return pk(__float2bfloat16(a), __float2bfloat16(b));
}
// D = A(bf16) * B(bf16) + D(f32), m16n8k16
static __device__ __forceinline__ void mma_bf16(
    float c[4], const u32 a[4], u32 b0, u32 b1)
{
    asm volatile(
        "mma.sync.aligned.m16n8k16.row.col.f32.bf16.bf16.f32 "
        "{%0,%1,%2,%3}, {%4,%5,%6,%7}, {%8,%9}, {%0,%1,%2,%3};"
        : "+f"(c[0]), "+f"(c[1]), "+f"(c[2]), "+f"(c[3])
        : "r"(a[0]), "r"(a[1]), "r"(a[2]), "r"(a[3]), "r"(b0), "r"(b1));
}
// split store: hi/lo bf16 of v at X[off]
static __device__ __forceinline__ void st_hl(
    __nv_bfloat16* Xh, __nv_bfloat16* Xl, int off, float v)
{
    __nv_bfloat16 hi = __float2bfloat16(v);
    Xh[off] = hi;
    Xl[off] = __float2bfloat16(v - __bfloat162float(hi));
}

// ---------------------------------------------------------------------------
// Layer 0: x[2048,512,28] -> h1 scratch.  K=92 pad 96 -> KS=6.
// ---------------------------------------------------------------------------
__global__ void __launch_bounds__(NTHR, 1)
lstm_l0(const float* __restrict__ x,
        const float* __restrict__ Wih, const float* __restrict__ Whh,
        const float* __restrict__ bih, const float* __restrict__ bhh)
{
    constexpr int KS = 6;
    __shared__ __nv_bfloat16 Xh[NB * XS], Xl[NB * XS];

    const int tid = threadIdx.x;
    const int wd = tid >> 5, lane = tid & 31;
    const int b0 = blockIdx.x * NB;

    for (int i = tid; i < NB * XS / 2; i += NTHR) {
        reinterpret_cast<u32*>(Xh)[i] = 0;
        reinterpret_cast<u32*>(Xl)[i] = 0;
    }

    // A fragments (weights) into registers, hi/lo split
    u32 Ah[2][KS][4], Al[2][KS][4];
#pragma unroll
    for (int mt = 0; mt < 2; mt++)
#pragma unroll
        for (int ks = 0; ks < KS; ks++)
#pragma unroll
            for (int rg = 0; rg < 4; rg++) {
                int rl = mt * 16 + (lane >> 2) + (rg & 1) * 8;
                int p = rl >> 3, jj = rl & 7, g = p * 64 + 8 * wd + jj;
                int k = ks * 16 + (lane & 3) * 2 + (rg >> 1) * 8;
                float w0 = 0.f, w1 = 0.f;
                if (k < IN_DIM)      w0 = Wih[g * IN_DIM + k];
                else if (k < 92)     w0 = Whh[g * H_DIM + k - IN_DIM];
                if (k + 1 < IN_DIM)  w1 = Wih[g * IN_DIM + k + 1];
                else if (k + 1 < 92) w1 = Whh[g * H_DIM + k + 1 - IN_DIM];
                __nv_bfloat16 h0 = __float2bfloat16(w0), h1 = __float2bfloat16(w1);
                Ah[mt][ks][rg] = pk(h0, h1);
                Al[mt][ks][rg] = pkf(w0 - __bfloat162float(h0),
                                     w1 - __bfloat162float(h1));
            }

    const int u  = 8 * wd + (lane >> 2);
    const int cp = lane & 3;
    const float bi = bih[u]       + bhh[u];
    const float bf = bih[64 + u]  + bhh[64 + u];
    const float bg = bih[128 + u] + bhh[128 + u];
    const float bo = bih[192 + u] + bhh[192 + u];
    const int hk = IN_DIM + u;     // X row (k index) for this unit's h

    float cst[4] = {0.f, 0.f, 0.f, 0.f};

    // x loader: 448 items; item0 all threads, item1 tid<192
    const int  xi1  = tid + NTHR;
    const bool act1 = (xi1 < NB * IN_DIM);
    const int  xb0 = tid / IN_DIM, xk0 = tid % IN_DIM;
    const int  xb1 = act1 ? xi1 / IN_DIM : 0, xk1 = act1 ? xi1 % IN_DIM : 0;
    const int  xo0 = xb0 * XS + xk0, xo1 = xb1 * XS + xk1;

    __syncthreads();   // zero-fill visible
    st_hl(Xh, Xl, xo0, x[((long long)(b0 + xb0) * T_STEPS) * IN_DIM + xk0]);
    if (act1)
        st_hl(Xh, Xl, xo1, x[((long long)(b0 + xb1) * T_STEPS) * IN_DIM + xk1]);

    for (int t = 0; t < T_STEPS; t++) {
        __syncthreads();   // bar1: X(t) complete

        float nx0 = 0.f, nx1 = 0.f;
        if (t + 1 < T_STEPS) {
            nx0 = x[((long long)(b0 + xb0) * T_STEPS + t + 1) * IN_DIM + xk0];
            if (act1)
                nx1 = x[((long long)(b0 + xb1) * T_STEPS + t + 1) * IN_DIM + xk1];
        }

        float C[2][2][4];
#pragma unroll
        for (int nt = 0; nt < 2; nt++) {
            C[0][nt][0] = bi; C[0][nt][1] = bi; C[0][nt][2] = bf; C[0][nt][3] = bf;
            C[1][nt][0] = bg; C[1][nt][1] = bg; C[1][nt][2] = bo; C[1][nt][3] = bo;
        }

#pragma unroll
        for (int ks = 0; ks < KS; ks++) {
            int kb = ks * 16 + cp * 2;
            u32 bh0[2], bh1[2], bl0[2], bl1[2];
#pragma unroll
            for (int nt = 0; nt < 2; nt++) {
                int n = nt * 8 + (lane >> 2);
                bh0[nt] = *reinterpret_cast<const u32*>(&Xh[n * XS + kb]);
                bh1[nt] = *reinterpret_cast<const u32*>(&Xh[n * XS + kb + 8]);
                bl0[nt] = *reinterpret_cast<const u32*>(&Xl[n * XS + kb]);
                bl1[nt] = *reinterpret_cast<const u32*>(&Xl[n * XS + kb + 8]);
            }
#pragma unroll
            for (int mt = 0; mt < 2; mt++)
#pragma unroll
                for (int nt = 0; nt < 2; nt++) {
                    mma_bf16(C[mt][nt], Ah[mt][ks], bh0[nt], bh1[nt]);
                    mma_bf16(C[mt][nt], Ah[mt][ks], bl0[nt], bl1[nt]);
                    mma_bf16(C[mt][nt], Al[mt][ks], bh0[nt], bh1[nt]);
                }
        }

        // cell update (fully thread-local): unit u, batches nt*8+2cp+col
        float h[4];
#pragma unroll
        for (int nt = 0; nt < 2; nt++)
#pragma unroll
            for (int col = 0; col < 2; col++) {
                int j = nt * 2 + col;
                float iv = sig_fast(C[0][nt][col]);
                float fv = sig_fast(C[0][nt][2 + col]);
                float gv = tanh_fast(C[1][nt][col]);
                float ov = sig_fast(C[1][nt][2 + col]);
                cst[j] = fmaf(fv, cst[j], iv * gv);
                h[j] = ov * tanh_fast(cst[j]);
            }
        __syncthreads();   // bar2: all X reads of step t done

#pragma unroll
        for (int j = 0; j < 4; j++) {
            int b = (j >> 1) * 8 + 2 * cp + (j & 1);
            st_hl(Xh, Xl, b * XS + hk, h[j]);
            g_h1[((long long)t * BATCH + b0 + b) * H_DIM + u] = h[j];
        }
        if (t + 1 < T_STEPS) {
            st_hl(Xh, Xl, xo0, nx0);
            if (act1) st_hl(Xh, Xl, xo1, nx1);
        }
    }
}

// ---------------------------------------------------------------------------
// Layer 1: h1 -> h2 -> out + r_last.  K=128 -> KS=8.
// ---------------------------------------------------------------------------
__global__ void __launch_bounds__(NTHR, 1)
lstm_l1(const float* __restrict__ Wih, const float* __restrict__ Whh,
        const float* __restrict__ bih, const float* __restrict__ bhh,
        const float* __restrict__ Wout, const float* __restrict__ bout,
        float* __restrict__ dout)
{
    constexpr int KS = 8;
    __shared__ __nv_bfloat16 Xh[NB * XS], Xl[NB * XS];
    __shared__ float hbuf[NB * H_DIM];

    const int tid = threadIdx.x;
    const int wd = tid >> 5, lane = tid & 31;
    const int b0 = blockIdx.x * NB;

    for (int i = tid; i < NB * XS / 2; i += NTHR) {
        reinterpret_cast<u32*>(Xh)[i] = 0;
        reinterpret_cast<u32*>(Xl)[i] = 0;
    }

    u32 Ah[2][KS][4], Al[2][KS][4];
#pragma unroll
    for (int mt = 0; mt < 2; mt++)
#pragma unroll
        for (int ks = 0; ks < KS; ks++)
#pragma unroll
            for (int rg = 0; rg < 4; rg++) {
                int rl = mt * 16 + (lane >> 2) + (rg & 1) * 8;
                int p = rl >> 3, jj = rl & 7, g = p * 64 + 8 * wd + jj;
                int k = ks * 16 + (lane & 3) * 2 + (rg >> 1) * 8;
                float w0 = (k < H_DIM) ? Wih[g * H_DIM + k]
                                       : Whh[g * H_DIM + k - H_DIM];
                float w1 = (k + 1 < H_DIM) ? Wih[g * H_DIM + k + 1]
                                           : Whh[g * H_DIM + k + 1 - H_DIM];
                __nv_bfloat16 h0 = __float2bfloat16(w0), h1 = __float2bfloat16(w1);
                Ah[mt][ks][rg] = pk(h0, h1);
                Al[mt][ks][rg] = pkf(w0 - __bfloat162float(h0),
                                     w1 - __bfloat162float(h1));
            }

    const int u  = 8 * wd + (lane >> 2);
    const int cp = lane & 3;
    const float bi = bih[u]       + bhh[u];
    const float bf = bih[64 + u]  + bhh[64 + u];
    const float bg = bih[128 + u] + bhh[128 + u];
    const float bo = bih[192 + u] + bhh[192 + u];
    const int hk = H_DIM + u;

    float cst[4] = {0.f, 0.f, 0.f, 0.f};

    // h1 loader: 1024 items, 2 iters x 2 consecutive u per thread (packed)
    int lb[2], lu[2];
#pragma unroll
    for (int j = 0; j < 2; j++) {
        int base = j * 512 + tid * 2;
        lb[j] = base >> 6; lu[j] = base & 63;
    }

    __syncthreads();
#pragma unroll
    for (int j = 0; j < 2; j++) {
        float2 v = *reinterpret_cast<const float2*>(
            g_h1 + (long long)(b0 + lb[j]) * H_DIM + lu[j]);
        int off = lb[j] * XS + lu[j];
        __nv_bfloat16 h0 = __float2bfloat16(v.x), h1 = __float2bfloat16(v.y);
        *reinterpret_cast<u32*>(&Xh[off]) = pk(h0, h1);
        *reinterpret_cast<u32*>(&Xl[off]) =
            pkf(v.x - __bfloat162float(h0), v.y - __bfloat162float(h1));
    }

    for (int t = 0; t < T_STEPS; t++) {
        __syncthreads();   // bar1

        float2 nh[2];
        if (t + 1 < T_STEPS) {
#pragma unroll
            for (int j = 0; j < 2; j++)
                nh[j] = *reinterpret_cast<const float2*>(
                    g_h1 + ((long long)(t + 1) * BATCH + b0 + lb[j]) * H_DIM + lu[j]);
        }

        float C[2][2][4];
#pragma unroll
        for (int nt = 0; nt < 2; nt++) {
            C[0][nt][0] = bi; C[0][nt][1] = bi; C[0][nt][2] = bf; C[0][nt][3] = bf;
            C[1][nt][0] = bg; C[1][nt][1] = bg; C[1][nt][2] = bo; C[1][nt][3] = bo;
        }

#pragma unroll
        for (int ks = 0; ks < KS; ks++) {
            int kb = ks * 16 + cp * 2;
            u32 bh0[2], bh1[2], bl0[2], bl1[2];
#pragma unroll
            for (int nt = 0; nt < 2; nt++) {
                int n = nt * 8 + (lane >> 2);
                bh0[nt] = *reinterpret_cast<const u32*>(&Xh[n * XS + kb]);
                bh1[nt] = *reinterpret_cast<const u32*>(&Xh[n * XS + kb + 8]);
                bl0[nt] = *reinterpret_cast<const u32*>(&Xl[n * XS + kb]);
                bl1[nt] = *reinterpret_cast<const u32*>(&Xl[n * XS + kb + 8]);
            }
#pragma unroll
            for (int mt = 0; mt < 2; mt++)
#pragma unroll
                for (int nt = 0; nt < 2; nt++) {
                    mma_bf16(C[mt][nt], Ah[mt][ks], bh0[nt], bh1[nt]);
                    mma_bf16(C[mt][nt], Ah[mt][ks], bl0[nt], bl1[nt]);
                    mma_bf16(C[mt][nt], Al[mt][ks], bh0[nt], bh1[nt]);
                }
        }

        float h[4];
#pragma unroll
        for (int nt = 0; nt < 2; nt++)
#pragma unroll
            for (int col = 0; col < 2; col++) {
                int j = nt * 2 + col;
                float iv = sig_fast(C[0][nt][col]);
                float fv = sig_fast(C[0][nt][2 + col]);
                float gv = tanh_fast(C[1][nt][col]);
                float ov = sig_fast(C[1][nt][2 + col]);
                cst[j] = fmaf(fv, cst[j], iv * gv);
                h[j] = ov * tanh_fast(cst[j]);
            }
        __syncthreads();   // bar2

#pragma unroll
        for (int j = 0; j < 4; j++) {
            int b = (j >> 1) * 8 + 2 * cp + (j & 1);
            st_hl(Xh, Xl, b * XS + hk, h[j]);
        }
        if (t + 1 < T_STEPS) {
#pragma unroll
            for (int j = 0; j < 2; j++) {
                int off = lb[j] * XS + lu[j];
                __nv_bfloat16 h0 = __float2bfloat16(nh[j].x),
                              h1 = __float2bfloat16(nh[j].y);
                *reinterpret_cast<u32*>(&Xh[off]) = pk(h0, h1);
                *reinterpret_cast<u32*>(&Xl[off]) =
                    pkf(nh[j].x - __bfloat162float(h0),
                        nh[j].y - __bfloat162float(h1));
            }
        } else {
#pragma unroll
            for (int j = 0; j < 4; j++) {
                int b = (j >> 1) * 8 + 2 * cp + (j & 1);
                hbuf[b * H_DIM + u] = h[j];
            }
        }
    }
    __syncthreads();   // hbuf visible

    // r_last
    for (int idx = tid; idx < NB * H_DIM; idx += NTHR) {
        int bl = idx >> 6, uu = idx & 63;
        dout[(long long)BATCH * OUT_DIM + (long long)(b0 + bl) * H_DIM + uu] =
            hbuf[bl * H_DIM + uu];
    }
    // out = h2 @ Wout^T + bout
    for (int i = tid; i < NB * OUT_DIM; i += NTHR) {
        int bl = i / OUT_DIM, o = i % OUT_DIM;
        float s = bout[o];
#pragma unroll
        for (int uu = 0; uu < H_DIM; uu++)
            s = fmaf(hbuf[bl * H_DIM + uu], Wout[o * H_DIM + uu], s);
        dout[(long long)(b0 + bl) * OUT_DIM + o] = s;
    }
}

// ---------------------------------------------------------------------------
extern "C" void kernel_launch(void* const* d_in, const int* in_sizes, int n_in,
                              void* d_out, int out_size)
{
    const float* x    = (const float*)d_in[0];
    const float* Wih0 = (const float*)d_in[1];
    const float* Whh0 = (const float*)d_in[2];
    const float* bih0 = (const float*)d_in[3];
    const float* bhh0 = (const float*)d_in[4];
    const float* Wih1 = (const float*)d_in[5];
    const float* Whh1 = (const float*)d_in[6];
    const float* bih1 = (const float*)d_in[7];
    const float* bhh1 = (const float*)d_in[8];
    const float* Wout = (const float*)d_in[9];
    const float* bout = (const float*)d_in[10];
    float* out = (float*)d_out;

    lstm_l0<<<NCTA, NTHR>>>(x, Wih0, Whh0, bih0, bhh0);
    lstm_l1<<<NCTA, NTHR>>>(Wih1, Whh1, bih1, bhh1, Wout, bout, out);
}

// round 12
// speedup vs baseline: 7.2626x; 1.2867x over previous
#include <cuda_runtime.h>
#include <cuda_fp16.h>

typedef unsigned int u32;

#define T_STEPS 512
#define BATCH   2048
#define IN_DIM  28
#define H_DIM   64
#define OUT_DIM 10
#define NB      16
#define NTHR    256
#define NCTA    (BATCH / NB)   // 128
#define XS      136            // X row stride in fp16 elems (conflict-free)

// Layer-0 hidden output scratch: [T][B][H] fp32
__device__ float g_h1[(long long)T_STEPS * BATCH * H_DIM];

static __device__ __forceinline__ float tanh_fast(float x) {
    float y; asm("tanh.approx.f32 %0, %1;" : "=f"(y) : "f"(x)); return y;
}
static __device__ __forceinline__ float sig_fast(float x) {
    return fmaf(0.5f, tanh_fast(0.5f * x), 0.5f);
}
static __device__ __forceinline__ u32 pkh(__half a, __half b) {
    __half2 t; t.x = a; t.y = b;
    return *reinterpret_cast<u32*>(&t);
}
// D = A(f16) * B(f16) + D(f32), m16n8k16
static __device__ __forceinline__ void mma_f16(
    float c[4], const u32 a[4], u32 b0, u32 b1)
{
    asm volatile(
        "mma.sync.aligned.m16n8k16.row.col.f32.f16.f16.f32 "
        "{%0,%1,%2,%3}, {%4,%5,%6,%7}, {%8,%9}, {%0,%1,%2,%3};"
        : "+f"(c[0]), "+f"(c[1]), "+f"(c[2]), "+f"(c[3])
        : "r"(a[0]), "r"(a[1]), "r"(a[2]), "r"(a[3]), "r"(b0), "r"(b1));
}
// split store: hi/lo fp16 of v
static __device__ __forceinline__ void st_hl(
    __half* Xh, __half* Xl, int off, float v)
{
    __half hi = __float2half_rn(v);
    Xh[off] = hi;
    Xl[off] = __float2half_rn(v - __half2float(hi));
}

// ---------------------------------------------------------------------------
// Layer 0: x[2048,512,28] -> h1 scratch.  K=92 pad 96 -> KS=6.
// ---------------------------------------------------------------------------
__global__ void __launch_bounds__(NTHR, 1)
lstm_l0(const float* __restrict__ x,
        const float* __restrict__ Wih, const float* __restrict__ Whh,
        const float* __restrict__ bih, const float* __restrict__ bhh)
{
    constexpr int KS = 6;
    __shared__ __half Xh[2][NB * XS], Xl[2][NB * XS];

    const int tid = threadIdx.x;
    const int wd = tid >> 5, lane = tid & 31;
    const int b0 = blockIdx.x * NB;

    for (int i = tid; i < NB * XS; i += NTHR) {
        Xh[0][i] = __float2half_rn(0.f); Xh[1][i] = __float2half_rn(0.f);
        Xl[0][i] = __float2half_rn(0.f); Xl[1][i] = __float2half_rn(0.f);
    }

    // A fragments (weights, single fp16) into registers
    u32 Ah[2][KS][4];
#pragma unroll
    for (int mt = 0; mt < 2; mt++)
#pragma unroll
        for (int ks = 0; ks < KS; ks++)
#pragma unroll
            for (int rg = 0; rg < 4; rg++) {
                int rl = mt * 16 + (lane >> 2) + (rg & 1) * 8;
                int p = rl >> 3, jj = rl & 7, g = p * 64 + 8 * wd + jj;
                int k = ks * 16 + (lane & 3) * 2 + (rg >> 1) * 8;
                float w0 = 0.f, w1 = 0.f;
                if (k < IN_DIM)      w0 = Wih[g * IN_DIM + k];
                else if (k < 92)     w0 = Whh[g * H_DIM + k - IN_DIM];
                if (k + 1 < IN_DIM)  w1 = Wih[g * IN_DIM + k + 1];
                else if (k + 1 < 92) w1 = Whh[g * H_DIM + k + 1 - IN_DIM];
                Ah[mt][ks][rg] = pkh(__float2half_rn(w0), __float2half_rn(w1));
            }

    const int u  = 8 * wd + (lane >> 2);
    const int cp = lane & 3;
    const float bi = bih[u]       + bhh[u];
    const float bf = bih[64 + u]  + bhh[64 + u];
    const float bg = bih[128 + u] + bhh[128 + u];
    const float bo = bih[192 + u] + bhh[192 + u];
    const int hk = IN_DIM + u;

    float cst[4] = {0.f, 0.f, 0.f, 0.f};

    // x loader: 448 items; item0 all threads, item1 tid<192
    const int  xi1  = tid + NTHR;
    const bool act1 = (xi1 < NB * IN_DIM);
    const int  xb0 = tid / IN_DIM, xk0 = tid % IN_DIM;
    const int  xb1 = act1 ? xi1 / IN_DIM : 0, xk1 = act1 ? xi1 % IN_DIM : 0;
    const int  xo0 = xb0 * XS + xk0, xo1 = xb1 * XS + xk1;

    __syncthreads();   // zero-fill visible
    st_hl(Xh[0], Xl[0], xo0, x[((long long)(b0 + xb0) * T_STEPS) * IN_DIM + xk0]);
    if (act1)
        st_hl(Xh[0], Xl[0], xo1, x[((long long)(b0 + xb1) * T_STEPS) * IN_DIM + xk1]);

    for (int t = 0; t < T_STEPS; t++) {
        const int cur = t & 1, nxt = cur ^ 1;
        __syncthreads();   // buf[cur] complete

        float nx0 = 0.f, nx1 = 0.f;
        if (t + 1 < T_STEPS) {
            nx0 = x[((long long)(b0 + xb0) * T_STEPS + t + 1) * IN_DIM + xk0];
            if (act1)
                nx1 = x[((long long)(b0 + xb1) * T_STEPS + t + 1) * IN_DIM + xk1];
        }

        float C[2][2][4], D[2][2][4];
#pragma unroll
        for (int nt = 0; nt < 2; nt++) {
            C[0][nt][0] = bi; C[0][nt][1] = bi; C[0][nt][2] = bf; C[0][nt][3] = bf;
            C[1][nt][0] = bg; C[1][nt][1] = bg; C[1][nt][2] = bo; C[1][nt][3] = bo;
#pragma unroll
            for (int mt = 0; mt < 2; mt++)
#pragma unroll
                for (int i = 0; i < 4; i++) D[mt][nt][i] = 0.f;
        }

#pragma unroll
        for (int ks = 0; ks < KS; ks++) {
            int kb = ks * 16 + cp * 2;
            u32 bh0[2], bh1[2], bl0[2], bl1[2];
#pragma unroll
            for (int nt = 0; nt < 2; nt++) {
                int n = nt * 8 + (lane >> 2);
                bh0[nt] = *reinterpret_cast<const u32*>(&Xh[cur][n * XS + kb]);
                bh1[nt] = *reinterpret_cast<const u32*>(&Xh[cur][n * XS + kb + 8]);
                bl0[nt] = *reinterpret_cast<const u32*>(&Xl[cur][n * XS + kb]);
                bl1[nt] = *reinterpret_cast<const u32*>(&Xl[cur][n * XS + kb + 8]);
            }
#pragma unroll
            for (int mt = 0; mt < 2; mt++)
#pragma unroll
                for (int nt = 0; nt < 2; nt++) {
                    mma_f16(C[mt][nt], Ah[mt][ks], bh0[nt], bh1[nt]);
                    mma_f16(D[mt][nt], Ah[mt][ks], bl0[nt], bl1[nt]);
                }
        }

        // cell update (thread-local): unit u, batches nt*8+2cp+col
        float h[4];
#pragma unroll
        for (int nt = 0; nt < 2; nt++)
#pragma unroll
            for (int col = 0; col < 2; col++) {
                int j = nt * 2 + col;
                float iv = sig_fast(C[0][nt][col]     + D[0][nt][col]);
                float fv = sig_fast(C[0][nt][2 + col] + D[0][nt][2 + col]);
                float gv = tanh_fast(C[1][nt][col]     + D[1][nt][col]);
                float ov = sig_fast(C[1][nt][2 + col] + D[1][nt][2 + col]);
                cst[j] = fmaf(fv, cst[j], iv * gv);
                h[j] = ov * tanh_fast(cst[j]);
            }

        // stores go to buf[nxt] — no second barrier needed
#pragma unroll
        for (int j = 0; j < 4; j++) {
            int b = (j >> 1) * 8 + 2 * cp + (j & 1);
            st_hl(Xh[nxt], Xl[nxt], b * XS + hk, h[j]);
            g_h1[((long long)t * BATCH + b0 + b) * H_DIM + u] = h[j];
        }
        if (t + 1 < T_STEPS) {
            st_hl(Xh[nxt], Xl[nxt], xo0, nx0);
            if (act1) st_hl(Xh[nxt], Xl[nxt], xo1, nx1);
        }
    }
}

// ---------------------------------------------------------------------------
// Layer 1: h1 -> h2 -> out + r_last.  K=128 -> KS=8.
// ---------------------------------------------------------------------------
__global__ void __launch_bounds__(NTHR, 1)
lstm_l1(const float* __restrict__ Wih, const float* __restrict__ Whh,
        const float* __restrict__ bih, const float* __restrict__ bhh,
        const float* __restrict__ Wout, const float* __restrict__ bout,
        float* __restrict__ dout)
{
    constexpr int KS = 8;
    __shared__ __half Xh[2][NB * XS], Xl[2][NB * XS];
    __shared__ float hbuf[NB * H_DIM];

    const int tid = threadIdx.x;
    const int wd = tid >> 5, lane = tid & 31;
    const int b0 = blockIdx.x * NB;

    for (int i = tid; i < NB * XS; i += NTHR) {
        Xh[0][i] = __float2half_rn(0.f); Xh[1][i] = __float2half_rn(0.f);
        Xl[0][i] = __float2half_rn(0.f); Xl[1][i] = __float2half_rn(0.f);
    }

    u32 Ah[2][KS][4];
#pragma unroll
    for (int mt = 0; mt < 2; mt++)
#pragma unroll
        for (int ks = 0; ks < KS; ks++)
#pragma unroll
            for (int rg = 0; rg < 4; rg++) {
                int rl = mt * 16 + (lane >> 2) + (rg & 1) * 8;
                int p = rl >> 3, jj = rl & 7, g = p * 64 + 8 * wd + jj;
                int k = ks * 16 + (lane & 3) * 2 + (rg >> 1) * 8;
                float w0 = (k < H_DIM) ? Wih[g * H_DIM + k]
                                       : Whh[g * H_DIM + k - H_DIM];
                float w1 = (k + 1 < H_DIM) ? Wih[g * H_DIM + k + 1]
                                           : Whh[g * H_DIM + k + 1 - H_DIM];
                Ah[mt][ks][rg] = pkh(__float2half_rn(w0), __float2half_rn(w1));
            }

    const int u  = 8 * wd + (lane >> 2);
    const int cp = lane & 3;
    const float bi = bih[u]       + bhh[u];
    const float bf = bih[64 + u]  + bhh[64 + u];
    const float bg = bih[128 + u] + bhh[128 + u];
    const float bo = bih[192 + u] + bhh[192 + u];
    const int hk = H_DIM + u;

    float cst[4] = {0.f, 0.f, 0.f, 0.f};

    // h1 loader: 1024 items, 2 iters x 2 consecutive u per thread
    int lb[2], lu[2];
#pragma unroll
    for (int j = 0; j < 2; j++) {
        int base = j * 512 + tid * 2;
        lb[j] = base >> 6; lu[j] = base & 63;
    }

    __syncthreads();
#pragma unroll
    for (int j = 0; j < 2; j++) {
        float2 v = *reinterpret_cast<const float2*>(
            g_h1 + (long long)(b0 + lb[j]) * H_DIM + lu[j]);
        int off = lb[j] * XS + lu[j];
        __half h0 = __float2half_rn(v.x), h1 = __float2half_rn(v.y);
        *reinterpret_cast<u32*>(&Xh[0][off]) = pkh(h0, h1);
        *reinterpret_cast<u32*>(&Xl[0][off]) =
            pkh(__float2half_rn(v.x - __half2float(h0)),
                __float2half_rn(v.y - __half2float(h1)));
    }

    for (int t = 0; t < T_STEPS; t++) {
        const int cur = t & 1, nxt = cur ^ 1;
        __syncthreads();   // buf[cur] complete

        float2 nh[2];
        if (t + 1 < T_STEPS) {
#pragma unroll
            for (int j = 0; j < 2; j++)
                nh[j] = *reinterpret_cast<const float2*>(
                    g_h1 + ((long long)(t + 1) * BATCH + b0 + lb[j]) * H_DIM + lu[j]);
        }

        float C[2][2][4], D[2][2][4];
#pragma unroll
        for (int nt = 0; nt < 2; nt++) {
            C[0][nt][0] = bi; C[0][nt][1] = bi; C[0][nt][2] = bf; C[0][nt][3] = bf;
            C[1][nt][0] = bg; C[1][nt][1] = bg; C[1][nt][2] = bo; C[1][nt][3] = bo;
#pragma unroll
            for (int mt = 0; mt < 2; mt++)
#pragma unroll
                for (int i = 0; i < 4; i++) D[mt][nt][i] = 0.f;
        }

#pragma unroll
        for (int ks = 0; ks < KS; ks++) {
            int kb = ks * 16 + cp * 2;
            u32 bh0[2], bh1[2], bl0[2], bl1[2];
#pragma unroll
            for (int nt = 0; nt < 2; nt++) {
                int n = nt * 8 + (lane >> 2);
                bh0[nt] = *reinterpret_cast<const u32*>(&Xh[cur][n * XS + kb]);
                bh1[nt] = *reinterpret_cast<const u32*>(&Xh[cur][n * XS + kb + 8]);
                bl0[nt] = *reinterpret_cast<const u32*>(&Xl[cur][n * XS + kb]);
                bl1[nt] = *reinterpret_cast<const u32*>(&Xl[cur][n * XS + kb + 8]);
            }
#pragma unroll
            for (int mt = 0; mt < 2; mt++)
#pragma unroll
                for (int nt = 0; nt < 2; nt++) {
                    mma_f16(C[mt][nt], Ah[mt][ks], bh0[nt], bh1[nt]);
                    mma_f16(D[mt][nt], Ah[mt][ks], bl0[nt], bl1[nt]);
                }
        }

        float h[4];
#pragma unroll
        for (int nt = 0; nt < 2; nt++)
#pragma unroll
            for (int col = 0; col < 2; col++) {
                int j = nt * 2 + col;
                float iv = sig_fast(C[0][nt][col]     + D[0][nt][col]);
                float fv = sig_fast(C[0][nt][2 + col] + D[0][nt][2 + col]);
                float gv = tanh_fast(C[1][nt][col]     + D[1][nt][col]);
                float ov = sig_fast(C[1][nt][2 + col] + D[1][nt][2 + col]);
                cst[j] = fmaf(fv, cst[j], iv * gv);
                h[j] = ov * tanh_fast(cst[j]);
            }

#pragma unroll
        for (int j = 0; j < 4; j++) {
            int b = (j >> 1) * 8 + 2 * cp + (j & 1);
            st_hl(Xh[nxt], Xl[nxt], b * XS + hk, h[j]);
        }
        if (t + 1 < T_STEPS) {
#pragma unroll
            for (int j = 0; j < 2; j++) {
                int off = lb[j] * XS + lu[j];
                __half h0 = __float2half_rn(nh[j].x), h1 = __float2half_rn(nh[j].y);
                *reinterpret_cast<u32*>(&Xh[nxt][off]) = pkh(h0, h1);
                *reinterpret_cast<u32*>(&Xl[nxt][off]) =
                    pkh(__float2half_rn(nh[j].x - __half2float(h0)),
                        __float2half_rn(nh[j].y - __half2float(h1)));
            }
        } else {
#pragma unroll
            for (int j = 0; j < 4; j++) {
                int b = (j >> 1) * 8 + 2 * cp + (j & 1);
                hbuf[b * H_DIM + u] = h[j];
            }
        }
    }
    __syncthreads();   // hbuf visible

    // r_last
    for (int idx = tid; idx < NB * H_DIM; idx += NTHR) {
        int bl = idx >> 6, uu = idx & 63;
        dout[(long long)BATCH * OUT_DIM + (long long)(b0 + bl) * H_DIM + uu] =
            hbuf[bl * H_DIM + uu];
    }
    // out = h2 @ Wout^T + bout
    for (int i = tid; i < NB * OUT_DIM; i += NTHR) {
        int bl = i / OUT_DIM, o = i % OUT_DIM;
        float s = bout[o];
#pragma unroll
        for (int uu = 0; uu < H_DIM; uu++)
            s = fmaf(hbuf[bl * H_DIM + uu], Wout[o * H_DIM + uu], s);
        dout[(long long)(b0 + bl) * OUT_DIM + o] = s;
    }
}

// ---------------------------------------------------------------------------
extern "C" void kernel_launch(void* const* d_in, const int* in_sizes, int n_in,
                              void* d_out, int out_size)
{
    const float* x    = (const float*)d_in[0];
    const float* Wih0 = (const float*)d_in[1];
    const float* Whh0 = (const float*)d_in[2];
    const float* bih0 = (const float*)d_in[3];
    const float* bhh0 = (const float*)d_in[4];
    const float* Wih1 = (const float*)d_in[5];
    const float* Whh1 = (const float*)d_in[6];
    const float* bih1 = (const float*)d_in[7];
    const float* bhh1 = (const float*)d_in[8];
    const float* Wout = (const float*)d_in[9];
    const float* bout = (const float*)d_in[10];
    float* out = (float*)d_out;

    lstm_l0<<<NCTA, NTHR>>>(x, Wih0, Whh0, bih0, bhh0);
    lstm_l1<<<NCTA, NTHR>>>(Wih1, Whh1, bih1, bhh1, Wout, bout, out);
}

// round 13
// speedup vs baseline: 8.5046x; 1.1710x over previous
#include <cuda_runtime.h>
#include <cuda_fp16.h>

typedef unsigned int u32;

#define T_STEPS 512
#define BATCH   2048
#define IN_DIM  28
#define H_DIM   64
#define OUT_DIM 10
#define NB      16
#define NTHR    512
#define NCTA    (BATCH / NB)   // 128
#define XS      136            // X row stride in fp16 elems (conflict-free)

// Layer-0 hidden output scratch: [T][B][H] fp32
__device__ float g_h1[(long long)T_STEPS * BATCH * H_DIM];

static __device__ __forceinline__ float tanh_fast(float x) {
    float y; asm("tanh.approx.f32 %0, %1;" : "=f"(y) : "f"(x)); return y;
}
static __device__ __forceinline__ float sig_fast(float x) {
    return fmaf(0.5f, tanh_fast(0.5f * x), 0.5f);
}
static __device__ __forceinline__ u32 pkh(__half a, __half b) {
    __half2 t; t.x = a; t.y = b;
    return *reinterpret_cast<u32*>(&t);
}
// D = A(f16) * B(f16) + D(f32), m16n8k16
static __device__ __forceinline__ void mma_f16(
    float c[4], const u32 a[4], u32 b0, u32 b1)
{
    asm volatile(
        "mma.sync.aligned.m16n8k16.row.col.f32.f16.f16.f32 "
        "{%0,%1,%2,%3}, {%4,%5,%6,%7}, {%8,%9}, {%0,%1,%2,%3};"
        : "+f"(c[0]), "+f"(c[1]), "+f"(c[2]), "+f"(c[3])
        : "r"(a[0]), "r"(a[1]), "r"(a[2]), "r"(a[3]), "r"(b0), "r"(b1));
}

// Warp tile: M=16 gate rows = [i u0..3 | f u0..3 | g u0..3 | o u0..3] for
// units 4w..4w+3; N=16 batches (2 n-tiles).  After MMA, lane L holds rows
// (r, r+8), r=lane>>2: r<4 -> {i_u, g_u}, r>=4 -> {f_u, o_u}, same u = 4w+(r&3)
// for partner lane L^16.  One select-exchange (2 shfl per n-tile) completes
// i,f,g,o per thread for batch b = nt*8 + 2*(lane&3) + (r>>2).

// ---------------------------------------------------------------------------
// Layer 0: x[2048,512,28] -> h1 scratch.  K=92 pad 96 -> KS=6.
// ---------------------------------------------------------------------------
__global__ void __launch_bounds__(NTHR, 1)
lstm_l0(const float* __restrict__ x,
        const float* __restrict__ Wih, const float* __restrict__ Whh,
        const float* __restrict__ bih, const float* __restrict__ bhh)
{
    constexpr int KS = 6;
    __shared__ __half Xh[2][NB * XS];

    const int tid = threadIdx.x;
    const int wd = tid >> 5, lane = tid & 31;
    const int b0 = blockIdx.x * NB;

    for (int i = tid; i < NB * XS; i += NTHR) {
        Xh[0][i] = __float2half_rn(0.f);
        Xh[1][i] = __float2half_rn(0.f);
    }

    // A fragments (weights fp16) into registers
    u32 Ah[KS][4];
#pragma unroll
    for (int ks = 0; ks < KS; ks++)
#pragma unroll
        for (int rg = 0; rg < 4; rg++) {
            int rl = (lane >> 2) + (rg & 1) * 8;
            int g = (rl >> 2) * 64 + 4 * wd + (rl & 3);
            int k = ks * 16 + (lane & 3) * 2 + (rg >> 1) * 8;
            float w0 = 0.f, w1 = 0.f;
            if (k < IN_DIM)      w0 = Wih[g * IN_DIM + k];
            else if (k < 92)     w0 = Whh[g * H_DIM + k - IN_DIM];
            if (k + 1 < IN_DIM)  w1 = Wih[g * IN_DIM + k + 1];
            else if (k + 1 < 92) w1 = Whh[g * H_DIM + k + 1 - IN_DIM];
            Ah[ks][rg] = pkh(__float2half_rn(w0), __float2half_rn(w1));
        }

    const int r    = lane >> 2;
    const int cp   = lane & 3;
    const int half = r >> 2;
    const int u    = 4 * wd + (r & 3);
    const int hk   = IN_DIM + u;

    // bias for this thread's two gate rows (travels through the exchange)
    const int gA = (half ? 1 : 0) * 64 + u;   // row r   : i or f
    const int gB = (half ? 3 : 2) * 64 + u;   // row r+8 : g or o
    const float bA = bih[gA] + bhh[gA];
    const float bB = bih[gB] + bhh[gB];

    float cst[2] = {0.f, 0.f};

    // x loader: 448 items over 512 threads
    const bool xact = (tid < NB * IN_DIM);
    const int  xb = xact ? tid / IN_DIM : 0, xk = xact ? tid % IN_DIM : 0;
    const int  xo = xb * XS + xk;

    __syncthreads();   // zero-fill visible
    if (xact)
        Xh[0][xo] = __float2half_rn(x[((long long)(b0 + xb) * T_STEPS) * IN_DIM + xk]);

    for (int t = 0; t < T_STEPS; t++) {
        const int cur = t & 1, nxt = cur ^ 1;
        __syncthreads();   // buf[cur] complete

        float nx = 0.f;
        if (xact && t + 1 < T_STEPS)
            nx = x[((long long)(b0 + xb) * T_STEPS + t + 1) * IN_DIM + xk];

        float C[2][4];
#pragma unroll
        for (int nt = 0; nt < 2; nt++) {
            C[nt][0] = bA; C[nt][1] = bA; C[nt][2] = bB; C[nt][3] = bB;
        }

#pragma unroll
        for (int ks = 0; ks < KS; ks++) {
            int kb = ks * 16 + cp * 2;
#pragma unroll
            for (int nt = 0; nt < 2; nt++) {
                int n = nt * 8 + r;
                u32 b0r = *reinterpret_cast<const u32*>(&Xh[cur][n * XS + kb]);
                u32 b1r = *reinterpret_cast<const u32*>(&Xh[cur][n * XS + kb + 8]);
                mma_f16(C[nt], Ah[ks], b0r, b1r);
            }
        }

        // exchange + cell update: thread handles batch b = nt*8 + 2cp + half
        float h[2];
#pragma unroll
        for (int nt = 0; nt < 2; nt++) {
            float s1 = half ? C[nt][0] : C[nt][1];
            float s2 = half ? C[nt][2] : C[nt][3];
            float rx1 = __shfl_xor_sync(0xFFFFFFFFu, s1, 16);
            float rx2 = __shfl_xor_sync(0xFFFFFFFFu, s2, 16);
            float iv = half ? rx1      : C[nt][0];
            float fv = half ? C[nt][1] : rx1;
            float gv = half ? rx2      : C[nt][2];
            float ov = half ? C[nt][3] : rx2;
            iv = sig_fast(iv); fv = sig_fast(fv);
            gv = tanh_fast(gv); ov = sig_fast(ov);
            cst[nt] = fmaf(fv, cst[nt], iv * gv);
            h[nt] = ov * tanh_fast(cst[nt]);
        }

        // stores go to buf[nxt] — single barrier per step
#pragma unroll
        for (int nt = 0; nt < 2; nt++) {
            int b = nt * 8 + 2 * cp + half;
            Xh[nxt][b * XS + hk] = __float2half_rn(h[nt]);
            g_h1[((long long)t * BATCH + b0 + b) * H_DIM + u] = h[nt];
        }
        if (xact && t + 1 < T_STEPS)
            Xh[nxt][xo] = __float2half_rn(nx);
    }
}

// ---------------------------------------------------------------------------
// Layer 1: h1 -> h2 -> out + r_last.  K=128 -> KS=8.
// ---------------------------------------------------------------------------
__global__ void __launch_bounds__(NTHR, 1)
lstm_l1(const float* __restrict__ Wih, const float* __restrict__ Whh,
        const float* __restrict__ bih, const float* __restrict__ bhh,
        const float* __restrict__ Wout, const float* __restrict__ bout,
        float* __restrict__ dout)
{
    constexpr int KS = 8;
    __shared__ __half Xh[2][NB * XS];
    __shared__ float hbuf[NB * H_DIM];

    const int tid = threadIdx.x;
    const int wd = tid >> 5, lane = tid & 31;
    const int b0 = blockIdx.x * NB;

    for (int i = tid; i < NB * XS; i += NTHR) {
        Xh[0][i] = __float2half_rn(0.f);
        Xh[1][i] = __float2half_rn(0.f);
    }

    u32 Ah[KS][4];
#pragma unroll
    for (int ks = 0; ks < KS; ks++)
#pragma unroll
        for (int rg = 0; rg < 4; rg++) {
            int rl = (lane >> 2) + (rg & 1) * 8;
            int g = (rl >> 2) * 64 + 4 * wd + (rl & 3);
            int k = ks * 16 + (lane & 3) * 2 + (rg >> 1) * 8;
            float w0 = (k < H_DIM) ? Wih[g * H_DIM + k]
                                   : Whh[g * H_DIM + k - H_DIM];
            float w1 = (k + 1 < H_DIM) ? Wih[g * H_DIM + k + 1]
                                       : Whh[g * H_DIM + k + 1 - H_DIM];
            Ah[ks][rg] = pkh(__float2half_rn(w0), __float2half_rn(w1));
        }

    const int r    = lane >> 2;
    const int cp   = lane & 3;
    const int half = r >> 2;
    const int u    = 4 * wd + (r & 3);
    const int hk   = H_DIM + u;

    const int gA = (half ? 1 : 0) * 64 + u;
    const int gB = (half ? 3 : 2) * 64 + u;
    const float bA = bih[gA] + bhh[gA];
    const float bB = bih[gB] + bhh[gB];

    float cst[2] = {0.f, 0.f};

    // h1 loader: 1024 items, one float2 per thread
    const int base = tid * 2;
    const int lb = base >> 6, lu = base & 63;
    const int lo = lb * XS + lu;

    __syncthreads();
    {
        float2 v = *reinterpret_cast<const float2*>(
            g_h1 + (long long)(b0 + lb) * H_DIM + lu);
        *reinterpret_cast<u32*>(&Xh[0][lo]) =
            pkh(__float2half_rn(v.x), __float2half_rn(v.y));
    }

    for (int t = 0; t < T_STEPS; t++) {
        const int cur = t & 1, nxt = cur ^ 1;
        __syncthreads();   // buf[cur] complete

        float2 nh = make_float2(0.f, 0.f);
        if (t + 1 < T_STEPS)
            nh = *reinterpret_cast<const float2*>(
                g_h1 + ((long long)(t + 1) * BATCH + b0 + lb) * H_DIM + lu);

        float C[2][4];
#pragma unroll
        for (int nt = 0; nt < 2; nt++) {
            C[nt][0] = bA; C[nt][1] = bA; C[nt][2] = bB; C[nt][3] = bB;
        }

#pragma unroll
        for (int ks = 0; ks < KS; ks++) {
            int kb = ks * 16 + cp * 2;
#pragma unroll
            for (int nt = 0; nt < 2; nt++) {
                int n = nt * 8 + r;
                u32 b0r = *reinterpret_cast<const u32*>(&Xh[cur][n * XS + kb]);
                u32 b1r = *reinterpret_cast<const u32*>(&Xh[cur][n * XS + kb + 8]);
                mma_f16(C[nt], Ah[ks], b0r, b1r);
            }
        }

        float h[2];
#pragma unroll
        for (int nt = 0; nt < 2; nt++) {
            float s1 = half ? C[nt][0] : C[nt][1];
            float s2 = half ? C[nt][2] : C[nt][3];
            float rx1 = __shfl_xor_sync(0xFFFFFFFFu, s1, 16);
            float rx2 = __shfl_xor_sync(0xFFFFFFFFu, s2, 16);
            float iv = half ? rx1      : C[nt][0];
            float fv = half ? C[nt][1] : rx1;
            float gv = half ? rx2      : C[nt][2];
            float ov = half ? C[nt][3] : rx2;
            iv = sig_fast(iv); fv = sig_fast(fv);
            gv = tanh_fast(gv); ov = sig_fast(ov);
            cst[nt] = fmaf(fv, cst[nt], iv * gv);
            h[nt] = ov * tanh_fast(cst[nt]);
        }

#pragma unroll
        for (int nt = 0; nt < 2; nt++) {
            int b = nt * 8 + 2 * cp + half;
            Xh[nxt][b * XS + hk] = __float2half_rn(h[nt]);
        }
        if (t + 1 < T_STEPS) {
            *reinterpret_cast<u32*>(&Xh[nxt][lo]) =
                pkh(__float2half_rn(nh.x), __float2half_rn(nh.y));
        } else {
#pragma unroll
            for (int nt = 0; nt < 2; nt++) {
                int b = nt * 8 + 2 * cp + half;
                hbuf[b * H_DIM + u] = h[nt];
            }
        }
    }
    __syncthreads();   // hbuf visible

    // r_last
    for (int idx = tid; idx < NB * H_DIM; idx += NTHR) {
        int bl = idx >> 6, uu = idx & 63;
        dout[(long long)BATCH * OUT_DIM + (long long)(b0 + bl) * H_DIM + uu] =
            hbuf[bl * H_DIM + uu];
    }
    // out = h2 @ Wout^T + bout
    for (int i = tid; i < NB * OUT_DIM; i += NTHR) {
        int bl = i / OUT_DIM, o = i % OUT_DIM;
        float s = bout[o];
#pragma unroll
        for (int uu = 0; uu < H_DIM; uu++)
            s = fmaf(hbuf[bl * H_DIM + uu], Wout[o * H_DIM + uu], s);
        dout[(long long)(b0 + bl) * OUT_DIM + o] = s;
    }
}

// ---------------------------------------------------------------------------
extern "C" void kernel_launch(void* const* d_in, const int* in_sizes, int n_in,
                              void* d_out, int out_size)
{
    const float* x    = (const float*)d_in[0];
    const float* Wih0 = (const float*)d_in[1];
    const float* Whh0 = (const float*)d_in[2];
    const float* bih0 = (const float*)d_in[3];
    const float* bhh0 = (const float*)d_in[4];
    const float* Wih1 = (const float*)d_in[5];
    const float* Whh1 = (const float*)d_in[6];
    const float* bih1 = (const float*)d_in[7];
    const float* bhh1 = (const float*)d_in[8];
    const float* Wout = (const float*)d_in[9];
    const float* bout = (const float*)d_in[10];
    float* out = (float*)d_out;

    lstm_l0<<<NCTA, NTHR>>>(x, Wih0, Whh0, bih0, bhh0);
    lstm_l1<<<NCTA, NTHR>>>(Wih1, Whh1, bih1, bhh1, Wout, bout, out);
}

// round 14
// speedup vs baseline: 11.8680x; 1.3955x over previous
#include <cuda_runtime.h>
#include <cuda_fp16.h>

typedef unsigned int u32;

#define T_STEPS 512
#define BATCH   2048
#define IN_DIM  28
#define H_DIM   64
#define OUT_DIM 10
#define NB      16
#define NTHR    512
#define NCTA    (BATCH / NB)   // 128
#define XS      136            // X row stride in fp16 elems (conflict-free)

static __device__ __forceinline__ float tanh_fast(float x) {
    float y; asm("tanh.approx.f32 %0, %1;" : "=f"(y) : "f"(x)); return y;
}
static __device__ __forceinline__ float sig_fast(float x) {
    return fmaf(0.5f, tanh_fast(0.5f * x), 0.5f);
}
static __device__ __forceinline__ u32 pkh(__half a, __half b) {
    __half2 t; t.x = a; t.y = b;
    return *reinterpret_cast<u32*>(&t);
}
// D = A(f16) * B(f16) + D(f32), m16n8k16
static __device__ __forceinline__ void mma_f16(
    float c[4], const u32 a[4], u32 b0, u32 b1)
{
    asm volatile(
        "mma.sync.aligned.m16n8k16.row.col.f32.f16.f16.f32 "
        "{%0,%1,%2,%3}, {%4,%5,%6,%7}, {%8,%9}, {%0,%1,%2,%3};"
        : "+f"(c[0]), "+f"(c[1]), "+f"(c[2]), "+f"(c[3])
        : "r"(a[0]), "r"(a[1]), "r"(a[2]), "r"(a[3]), "r"(b0), "r"(b1));
}

// Warp-tile per m-tile: M=16 gate rows = [i u0..3 | f u0..3 | g u0..3 | o u0..3]
// for units ubase..ubase+3.  After MMA, the xor-16 select-exchange completes
// i,f,g,o per thread for (unit ubase+(r&3), batch nt*8+2cp+half).
// Fused pipeline: warps 0-7 = layer0 step t; warps 8-15 = layer1 step t-1.
// X0[p]: l0 input (cols 0-27 x, 28-91 h0); X1[p]: l1 input (0-63 h1, 64-127 h2).
// iter t: l0 reads X0[t&1], writes X0[t&1^1] + h1 -> X1[t&1];
//         l1 reads X1[t&1^1],  writes h2 -> X1[t&1].  One barrier per iter.

__global__ void __launch_bounds__(NTHR, 1)
lstm_fused(const float* __restrict__ x,
           const float* __restrict__ Wih0, const float* __restrict__ Whh0,
           const float* __restrict__ bih0, const float* __restrict__ bhh0,
           const float* __restrict__ Wih1, const float* __restrict__ Whh1,
           const float* __restrict__ bih1, const float* __restrict__ bhh1,
           const float* __restrict__ Wout, const float* __restrict__ bout,
           float* __restrict__ dout)
{
    __shared__ __half X0[2][NB * XS];
    __shared__ __half X1[2][NB * XS];
    __shared__ float  hbuf[NB * H_DIM];

    const int tid = threadIdx.x;
    const int wd = tid >> 5, lane = tid & 31;
    const int b0 = blockIdx.x * NB;

    for (int i = tid; i < NB * XS; i += NTHR) {
        __half z = __float2half_rn(0.f);
        X0[0][i] = z; X0[1][i] = z; X1[0][i] = z; X1[1][i] = z;
    }
    __syncthreads();   // barrier #1 (both groups)

    const int r    = lane >> 2;
    const int cp   = lane & 3;
    const int half = r >> 2;
    const int grp  = wd >> 3;
    const int wg   = wd & 7;

    if (grp == 0) {
        // ================= layer 0 (warps 0-7) =================
        constexpr int KS = 6;
        u32 A[2][KS][4];
#pragma unroll
        for (int mt = 0; mt < 2; mt++) {
            int ubase = 8 * wg + 4 * mt;
#pragma unroll
            for (int ks = 0; ks < KS; ks++)
#pragma unroll
                for (int rg = 0; rg < 4; rg++) {
                    int rl = r + (rg & 1) * 8;
                    int g = (rl >> 2) * 64 + ubase + (rl & 3);
                    int k = ks * 16 + cp * 2 + (rg >> 1) * 8;
                    float w0 = 0.f, w1 = 0.f;
                    if (k < IN_DIM)      w0 = Wih0[g * IN_DIM + k];
                    else if (k < 92)     w0 = Whh0[g * H_DIM + k - IN_DIM];
                    if (k + 1 < IN_DIM)  w1 = Wih0[g * IN_DIM + k + 1];
                    else if (k + 1 < 92) w1 = Whh0[g * H_DIM + k + 1 - IN_DIM];
                    A[mt][ks][rg] = pkh(__float2half_rn(w0), __float2half_rn(w1));
                }
        }
        float bA[2], bB[2];
        int uu[2];
#pragma unroll
        for (int mt = 0; mt < 2; mt++) {
            uu[mt] = 8 * wg + 4 * mt + (r & 3);
            int gA = (half ? 1 : 0) * 64 + uu[mt];
            int gB = (half ? 3 : 2) * 64 + uu[mt];
            bA[mt] = bih0[gA] + bhh0[gA];
            bB[mt] = bih0[gB] + bhh0[gB];
        }
        float cst[2][2] = {{0.f, 0.f}, {0.f, 0.f}};

        // x loader: 448 items over 256 grp0 threads
        const int  i1 = tid + 256;
        const bool a1 = (i1 < NB * IN_DIM);
        const int  xb0 = tid / IN_DIM, xk0 = tid % IN_DIM, xo0 = xb0 * XS + xk0;
        const int  xb1 = a1 ? i1 / IN_DIM : 0, xk1 = a1 ? i1 % IN_DIM : 0;
        const int  xo1 = xb1 * XS + xk1;

        // pre-store x(0) into X0[0]
        X0[0][xo0] = __float2half_rn(
            x[((long long)(b0 + xb0) * T_STEPS) * IN_DIM + xk0]);
        if (a1)
            X0[0][xo1] = __float2half_rn(
                x[((long long)(b0 + xb1) * T_STEPS) * IN_DIM + xk1]);

        for (int t = 0; t <= T_STEPS; t++) {
            __syncthreads();             // loop barriers (513)
            if (t >= T_STEPS) continue;
            const int cur = t & 1, oth = cur ^ 1;

            float nx0 = 0.f, nx1 = 0.f;
            if (t + 1 < T_STEPS) {
                nx0 = x[((long long)(b0 + xb0) * T_STEPS + t + 1) * IN_DIM + xk0];
                if (a1)
                    nx1 = x[((long long)(b0 + xb1) * T_STEPS + t + 1) * IN_DIM + xk1];
            }

            float C[2][2][4];
#pragma unroll
            for (int mt = 0; mt < 2; mt++)
#pragma unroll
                for (int nt = 0; nt < 2; nt++) {
                    C[mt][nt][0] = bA[mt]; C[mt][nt][1] = bA[mt];
                    C[mt][nt][2] = bB[mt]; C[mt][nt][3] = bB[mt];
                }
#pragma unroll
            for (int ks = 0; ks < KS; ks++) {
                int kb = ks * 16 + cp * 2;
#pragma unroll
                for (int nt = 0; nt < 2; nt++) {
                    int n = nt * 8 + r;
                    u32 q0 = *reinterpret_cast<const u32*>(&X0[cur][n * XS + kb]);
                    u32 q1 = *reinterpret_cast<const u32*>(&X0[cur][n * XS + kb + 8]);
                    mma_f16(C[0][nt], A[0][ks], q0, q1);
                    mma_f16(C[1][nt], A[1][ks], q0, q1);
                }
            }

#pragma unroll
            for (int mt = 0; mt < 2; mt++)
#pragma unroll
                for (int nt = 0; nt < 2; nt++) {
                    float s1 = half ? C[mt][nt][0] : C[mt][nt][1];
                    float s2 = half ? C[mt][nt][2] : C[mt][nt][3];
                    float rx1 = __shfl_xor_sync(0xFFFFFFFFu, s1, 16);
                    float rx2 = __shfl_xor_sync(0xFFFFFFFFu, s2, 16);
                    float iv = half ? rx1          : C[mt][nt][0];
                    float fv = half ? C[mt][nt][1] : rx1;
                    float gv = half ? rx2          : C[mt][nt][2];
                    float ov = half ? C[mt][nt][3] : rx2;
                    iv = sig_fast(iv); fv = sig_fast(fv);
                    gv = tanh_fast(gv); ov = sig_fast(ov);
                    cst[mt][nt] = fmaf(fv, cst[mt][nt], iv * gv);
                    float h = ov * tanh_fast(cst[mt][nt]);
                    int b = nt * 8 + 2 * cp + half;
                    __half hh = __float2half_rn(h);
                    X0[oth][b * XS + IN_DIM + uu[mt]] = hh;  // h0 recurrent
                    X1[cur][b * XS + uu[mt]]          = hh;  // h1 -> layer1
                }

            if (t + 1 < T_STEPS) {
                X0[oth][xo0] = __float2half_rn(nx0);
                if (a1) X0[oth][xo1] = __float2half_rn(nx1);
            }
        }
    } else {
        // ================= layer 1 (warps 8-15), step t-1 =================
        constexpr int KS = 8;
        u32 A[2][KS][4];
#pragma unroll
        for (int mt = 0; mt < 2; mt++) {
            int ubase = 8 * wg + 4 * mt;
#pragma unroll
            for (int ks = 0; ks < KS; ks++)
#pragma unroll
                for (int rg = 0; rg < 4; rg++) {
                    int rl = r + (rg & 1) * 8;
                    int g = (rl >> 2) * 64 + ubase + (rl & 3);
                    int k = ks * 16 + cp * 2 + (rg >> 1) * 8;
                    float w0 = (k < H_DIM) ? Wih1[g * H_DIM + k]
                                           : Whh1[g * H_DIM + k - H_DIM];
                    float w1 = (k + 1 < H_DIM) ? Wih1[g * H_DIM + k + 1]
                                               : Whh1[g * H_DIM + k + 1 - H_DIM];
                    A[mt][ks][rg] = pkh(__float2half_rn(w0), __float2half_rn(w1));
                }
        }
        float bA[2], bB[2];
        int uu[2];
#pragma unroll
        for (int mt = 0; mt < 2; mt++) {
            uu[mt] = 8 * wg + 4 * mt + (r & 3);
            int gA = (half ? 1 : 0) * 64 + uu[mt];
            int gB = (half ? 3 : 2) * 64 + uu[mt];
            bA[mt] = bih1[gA] + bhh1[gA];
            bB[mt] = bih1[gB] + bhh1[gB];
        }
        float cst[2][2] = {{0.f, 0.f}, {0.f, 0.f}};

        for (int t = 0; t <= T_STEPS; t++) {
            __syncthreads();             // loop barriers (513)
            if (t == 0) continue;
            const int cur = t & 1, oth = cur ^ 1;

            float C[2][2][4];
#pragma unroll
            for (int mt = 0; mt < 2; mt++)
#pragma unroll
                for (int nt = 0; nt < 2; nt++) {
                    C[mt][nt][0] = bA[mt]; C[mt][nt][1] = bA[mt];
                    C[mt][nt][2] = bB[mt]; C[mt][nt][3] = bB[mt];
                }
#pragma unroll
            for (int ks = 0; ks < KS; ks++) {
                int kb = ks * 16 + cp * 2;
#pragma unroll
                for (int nt = 0; nt < 2; nt++) {
                    int n = nt * 8 + r;
                    u32 q0 = *reinterpret_cast<const u32*>(&X1[oth][n * XS + kb]);
                    u32 q1 = *reinterpret_cast<const u32*>(&X1[oth][n * XS + kb + 8]);
                    mma_f16(C[0][nt], A[0][ks], q0, q1);
                    mma_f16(C[1][nt], A[1][ks], q0, q1);
                }
            }

#pragma unroll
            for (int mt = 0; mt < 2; mt++)
#pragma unroll
                for (int nt = 0; nt < 2; nt++) {
                    float s1 = half ? C[mt][nt][0] : C[mt][nt][1];
                    float s2 = half ? C[mt][nt][2] : C[mt][nt][3];
                    float rx1 = __shfl_xor_sync(0xFFFFFFFFu, s1, 16);
                    float rx2 = __shfl_xor_sync(0xFFFFFFFFu, s2, 16);
                    float iv = half ? rx1          : C[mt][nt][0];
                    float fv = half ? C[mt][nt][1] : rx1;
                    float gv = half ? rx2          : C[mt][nt][2];
                    float ov = half ? C[mt][nt][3] : rx2;
                    iv = sig_fast(iv); fv = sig_fast(fv);
                    gv = tanh_fast(gv); ov = sig_fast(ov);
                    cst[mt][nt] = fmaf(fv, cst[mt][nt], iv * gv);
                    float h = ov * tanh_fast(cst[mt][nt]);
                    int b = nt * 8 + 2 * cp + half;
                    X1[cur][b * XS + H_DIM + uu[mt]] = __float2half_rn(h);
                    if (t == T_STEPS)
                        hbuf[b * H_DIM + uu[mt]] = h;
                }
        }
    }
    __syncthreads();   // final barrier (both groups)

    // epilogue (all 512 threads): r_last + out
    for (int idx = tid; idx < NB * H_DIM; idx += NTHR) {
        int bl = idx >> 6, u2 = idx & 63;
        dout[(long long)BATCH * OUT_DIM + (long long)(b0 + bl) * H_DIM + u2] =
            hbuf[bl * H_DIM + u2];
    }
    for (int i = tid; i < NB * OUT_DIM; i += NTHR) {
        int bl = i / OUT_DIM, o = i % OUT_DIM;
        float s = bout[o];
#pragma unroll
        for (int u2 = 0; u2 < H_DIM; u2++)
            s = fmaf(hbuf[bl * H_DIM + u2], Wout[o * H_DIM + u2], s);
        dout[(long long)(b0 + bl) * OUT_DIM + o] = s;
    }
}

// ---------------------------------------------------------------------------
extern "C" void kernel_launch(void* const* d_in, const int* in_sizes, int n_in,
                              void* d_out, int out_size)
{
    const float* x    = (const float*)d_in[0];
    const float* Wih0 = (const float*)d_in[1];
    const float* Whh0 = (const float*)d_in[2];
    const float* bih0 = (const float*)d_in[3];
    const float* bhh0 = (const float*)d_in[4];
    const float* Wih1 = (const float*)d_in[5];
    const float* Whh1 = (const float*)d_in[6];
    const float* bih1 = (const float*)d_in[7];
    const float* bhh1 = (const float*)d_in[8];
    const float* Wout = (const float*)d_in[9];
    const float* bout = (const float*)d_in[10];
    float* out = (float*)d_out;

    lstm_fused<<<NCTA, NTHR>>>(x, Wih0, Whh0, bih0, bhh0,
                               Wih1, Whh1, bih1, bhh1, Wout, bout, out);
}